// round 7
// baseline (speedup 1.0000x reference)
#include <cuda_runtime.h>
#include <cstddef>
#include <cstdint>

// Problem constants
#define Bb 8
#define Np 8192
#define Mp 1024
#define Cc 256
#define Rr (Bb*Np)       // 65536 rows
#define BN_EPS 1e-5f

// Scratch (static __device__ — no allocations allowed)
__device__ float g_bufA[(size_t)Rr*Cc];     // 64 MB
__device__ float g_bufB[(size_t)Rr*Cc];     // 64 MB
__device__ float g_xT[(size_t)Bb*Mp*Cc];    // 8 MB
__device__ uint4 g_wcv[16384];              // 256 KB: W pre-converted stage image
__device__ float g_sum[Cc];
__device__ float g_sumsq[Cc];
__device__ float g_scale[Cc];
__device__ float g_shift[Cc];

// ---------------------------------------------------------------------------
__global__ void zero_stats_kernel() {
    int t = threadIdx.x;
    g_sum[t] = 0.f; g_sumsq[t] = 0.f;
}

// ---------------------------------------------------------------------------
// transpose x[b][c][m] -> xT[b][m][c]
__global__ void transpose_x_kernel(const float* __restrict__ x, float* __restrict__ xT) {
    __shared__ float t[32][33];
    int b = blockIdx.z;
    int m0 = blockIdx.x * 32, c0 = blockIdx.y * 32;
    int tx = threadIdx.x, ty = threadIdx.y; // 32 x 8
    const float* xb = x + (size_t)b * Cc * Mp;
    #pragma unroll
    for (int k = 0; k < 32; k += 8)
        t[ty + k][tx] = xb[(size_t)(c0 + ty + k) * Mp + m0 + tx];
    __syncthreads();
    float* ob = xT + (size_t)b * Mp * Cc;
    #pragma unroll
    for (int k = 0; k < 32; k += 8)
        ob[(size_t)(m0 + ty + k) * Cc + c0 + tx] = t[tx][ty + k];
}

// ---------------------------------------------------------------------------
// 3-NN + inverse-distance-weighted interpolation. Writes h0 in [b][n][c].
// Even/odd 2-chain top-3 scan for ILP; float4-vectorized gather.
__global__ void knn_interp_kernel(const float* __restrict__ p,
                                  const float* __restrict__ q,
                                  const float* __restrict__ xT,
                                  float* __restrict__ h0) {
    __shared__ float sqx[Mp], sqy[Mp], sqz[Mp], sqq[Mp];
    __shared__ float sw[128][3];
    __shared__ int   si[128][3];
    const int b = blockIdx.x;
    const int n0 = blockIdx.y * 128;
    const int tid = threadIdx.x;

    for (int m = tid; m < Mp; m += 128) {
        float qx = q[((size_t)b * Mp + m) * 3 + 0];
        float qy = q[((size_t)b * Mp + m) * 3 + 1];
        float qz = q[((size_t)b * Mp + m) * 3 + 2];
        sqx[m] = qx; sqy[m] = qy; sqz[m] = qz;
        sqq[m] = qx * qx + qy * qy + qz * qz;
    }
    __syncthreads();

    const int n = n0 + tid;
    float px = p[((size_t)b * Np + n) * 3 + 0];
    float py = p[((size_t)b * Np + n) * 3 + 1];
    float pz = p[((size_t)b * Np + n) * 3 + 2];
    float pp = px * px + py * py + pz * pz;

    float e0 = 3.4e38f, e1 = 3.4e38f, e2 = 3.4e38f;
    int   ei0 = 0, ei1 = 0, ei2 = 0;
    float o0 = 3.4e38f, o1 = 3.4e38f, o2 = 3.4e38f;
    int   oi0 = 0, oi1 = 0, oi2 = 0;
    #pragma unroll 2
    for (int m = 0; m < Mp; m += 2) {
        float dotE = px * sqx[m] + py * sqy[m] + pz * sqz[m];
        float dE = pp + sqq[m] - 2.f * dotE;
        float dotO = px * sqx[m+1] + py * sqy[m+1] + pz * sqz[m+1];
        float dO = pp + sqq[m+1] - 2.f * dotO;
        if (dE < e2) {
            if (dE < e1) {
                e2 = e1; ei2 = ei1;
                if (dE < e0) { e1 = e0; ei1 = ei0; e0 = dE; ei0 = m; }
                else         { e1 = dE; ei1 = m; }
            } else { e2 = dE; ei2 = m; }
        }
        if (dO < o2) {
            if (dO < o1) {
                o2 = o1; oi2 = oi1;
                if (dO < o0) { o1 = o0; oi1 = oi0; o0 = dO; oi0 = m+1; }
                else         { o1 = dO; oi1 = m+1; }
            } else { o2 = dO; oi2 = m+1; }
        }
    }
    #pragma unroll
    for (int c = 0; c < 3; c++) {
        float d = (c == 0) ? o0 : (c == 1) ? o1 : o2;
        int   i = (c == 0) ? oi0 : (c == 1) ? oi1 : oi2;
        if (d < e2) {
            if (d < e1) {
                e2 = e1; ei2 = ei1;
                if (d < e0) { e1 = e0; ei1 = ei0; e0 = d; ei0 = i; }
                else        { e1 = d; ei1 = i; }
            } else { e2 = d; ei2 = i; }
        }
    }
    float a0 = 1.f / fmaxf(e0, 1e-10f);
    float a1 = 1.f / fmaxf(e1, 1e-10f);
    float a2 = 1.f / fmaxf(e2, 1e-10f);
    float inv = 1.f / (a0 + a1 + a2);
    sw[tid][0] = a0 * inv; sw[tid][1] = a1 * inv; sw[tid][2] = a2 * inv;
    si[tid][0] = ei0; si[tid][1] = ei1; si[tid][2] = ei2;
    __syncthreads();

    const int lane = tid & 31, warp = tid >> 5;
    const float* xb = xT + (size_t)b * Mp * Cc;
    for (int nl = warp * 32; nl < warp * 32 + 32; nl++) {
        float w0 = sw[nl][0], w1 = sw[nl][1], w2 = sw[nl][2];
        const float4* r0 = (const float4*)(xb + (size_t)si[nl][0] * Cc);
        const float4* r1 = (const float4*)(xb + (size_t)si[nl][1] * Cc);
        const float4* r2 = (const float4*)(xb + (size_t)si[nl][2] * Cc);
        float4* o4 = (float4*)(h0 + ((size_t)b * Np + n0 + nl) * Cc);
        #pragma unroll
        for (int c = lane; c < Cc / 4; c += 32) {
            float4 a = r0[c], bq = r1[c], cq = r2[c];
            float4 v;
            v.x = w0 * a.x + w1 * bq.x + w2 * cq.x;
            v.y = w0 * a.y + w1 * bq.y + w2 * cq.y;
            v.z = w0 * a.z + w1 * bq.z + w2 * cq.z;
            v.w = w0 * a.w + w1 * bq.w + w2 * cq.w;
            o4[c] = v;
        }
    }
}

// ---------------------------------------------------------------------------
// bf16x3 emulated-fp32 GEMM via legacy mma.sync (sm_80 PTX path)
// ---------------------------------------------------------------------------
__device__ __forceinline__ uint32_t prmt_hi(uint32_t a, uint32_t b) {
    uint32_t r; asm("prmt.b32 %0, %1, %2, 0x7632;" : "=r"(r) : "r"(a), "r"(b));
    return r;   // {lo16 = a.hi16, hi16 = b.hi16}
}
__device__ __forceinline__ uint32_t pack_bf16_rn(float lo0, float lo1) {
    uint32_t r; asm("cvt.rn.bf16x2.f32 %0, %1, %2;" : "=r"(r) : "f"(lo1), "f"(lo0));
    return r;   // low half = lo0
}
__device__ __forceinline__ float trunc_hi_f(float f) {
    return __uint_as_float(__float_as_uint(f) & 0xFFFF0000u);
}

#define MMA_BF16(c, a, b0v, b1v) \
    asm volatile("mma.sync.aligned.m16n8k16.row.col.f32.bf16.bf16.f32 " \
        "{%0,%1,%2,%3},{%4,%5,%6,%7},{%8,%9},{%0,%1,%2,%3};" \
        : "+f"((c)[0]), "+f"((c)[1]), "+f"((c)[2]), "+f"((c)[3]) \
        : "r"((a).x), "r"((a).y), "r"((a).z), "r"((a).w), "r"(b0v), "r"(b1v))

#define LDMATRIX_X4(r, addr) \
    asm volatile("ldmatrix.sync.aligned.m8n8.x4.shared.b16 {%0,%1,%2,%3}, [%4];" \
        : "=r"((r).x), "=r"((r).y), "=r"((r).z), "=r"((r).w) : "r"(addr))

#define CP_ASYNC16(dst, src) \
    asm volatile("cp.async.ca.shared.global [%0], [%1], 16;" :: "r"(dst), "l"(src))

// smem tiles: bf16, row-major, 128 rows x 32 k = 64 B/row, XOR-granule swizzle.
// addr(row, kg) = row*64 + (kg ^ ((row>>1)&3))*16        (kg = 16B granule 0..3)
#define TILE_B    8192                // one 128x32 bf16 tile
#define STAGE3_B  (4 * TILE_B)        // A_hi, A_lo, B_hi, B_lo = 32 KB
#define SMEM_GEMM_BYTES (3 * STAGE3_B) // 3-stage ring = 98304 B

// ---------------------------------------------------------------------------
// W pre-convert: exact B-stage smem image per (nblock, kb) chunk:
// chunk = 16 KB: [hi tile 8 KB | lo tile 8 KB], swizzle baked into addresses.
__global__ void wconv_kernel(const float* __restrict__ W, uint4* __restrict__ wcv) {
    const int nb = blockIdx.x, kb = blockIdx.y;
    const int tid = threadIdx.x;
    const int r = tid >> 2;               // row within 128
    const int c16 = tid & 3;              // granule within row
    const int kg = c16 ^ ((r >> 1) & 3);  // inverse swizzle -> logical granule
    const float* src = W + (size_t)(nb * 128 + r) * 256 + kb * 32 + kg * 8;
    float4 v0 = *(const float4*)src;
    float4 v1 = *(const float4*)(src + 4);
    float a[8] = {v0.x, v0.y, v0.z, v0.w, v1.x, v1.y, v1.z, v1.w};
    uint4 hi, lo;
    hi.x = prmt_hi(__float_as_uint(a[0]), __float_as_uint(a[1]));
    hi.y = prmt_hi(__float_as_uint(a[2]), __float_as_uint(a[3]));
    hi.z = prmt_hi(__float_as_uint(a[4]), __float_as_uint(a[5]));
    hi.w = prmt_hi(__float_as_uint(a[6]), __float_as_uint(a[7]));
    lo.x = pack_bf16_rn(a[0] - trunc_hi_f(a[0]), a[1] - trunc_hi_f(a[1]));
    lo.y = pack_bf16_rn(a[2] - trunc_hi_f(a[2]), a[3] - trunc_hi_f(a[3]));
    lo.z = pack_bf16_rn(a[4] - trunc_hi_f(a[4]), a[5] - trunc_hi_f(a[5]));
    lo.w = pack_bf16_rn(a[6] - trunc_hi_f(a[6]), a[7] - trunc_hi_f(a[7]));
    const size_t base = (size_t)(nb * 8 + kb) * 1024;   // 1024 granules per chunk
    wcv[base + tid]       = hi;
    wcv[base + 512 + tid] = lo;
}

// ---------------------------------------------------------------------------
// out[r][o] = sum_c act(A[r][c]) * W[o][c] + bias[o], K=256, tile 128x128.
// 512 threads, 16 warps (4M x 4N). 3-stage ring: B via cp.async (dist 2),
// A via register prefetch (dist 2) + early storeS. BN stats fused epilogue.
__global__ void __launch_bounds__(512)
gemm_bf16x3_kernel(const float* __restrict__ A, const uint4* __restrict__ wcv,
                   const float* __restrict__ bias, int useAct,
                   float* __restrict__ out, int O) {
    extern __shared__ char smc[];
    const int tid = threadIdx.x;
    const int lane = tid & 31, wid = tid >> 5;
    const int wm = wid >> 2, wn = wid & 3;
    const size_t rowBase = (size_t)blockIdx.x * 128;
    const int colBase = blockIdx.y * 128;

    const uint32_t smb = (uint32_t)__cvta_generic_to_shared(smc);

    // producer A mapping: row = tid>>2 (0..127), kg = tid&3 (8 k each)
    const int prow = tid >> 2;
    const int pkg = tid & 3;
    const uint32_t pOff = (uint32_t)(prow * 64 + ((pkg ^ ((prow >> 1) & 3)) << 4));
    const float* aG = A + (rowBase + prow) * 256 + pkg * 8;

    const char* wsrc = (const char*)(wcv + (size_t)blockIdx.y * 8 * 1024);

    float acc[2][4][4];
    #pragma unroll
    for (int i = 0; i < 2; i++)
        #pragma unroll
        for (int j = 0; j < 4; j++)
            #pragma unroll
            for (int r = 0; r < 4; r++) acc[i][j][r] = 0.f;

    float4 va[2][2];   // two prefetch register sets
    auto loadG = [&](int kb, int set) {
        va[set][0] = *(const float4*)(aG + kb * 32);
        va[set][1] = *(const float4*)(aG + kb * 32 + 4);
    };
    auto cpB = [&](int st, int kb) {
        const char* src = wsrc + (size_t)kb * 2 * TILE_B + tid * 16;
        uint32_t d = smb + st * STAGE3_B + 2 * TILE_B + tid * 16;
        CP_ASYNC16(d, src);
        CP_ASYNC16(d + TILE_B, src + TILE_B);
        asm volatile("cp.async.commit_group;");
    };
    auto storeS = [&](int st, int set, int kb) {
        uint32_t base = smb + st * STAGE3_B + pOff;
        float a[8] = {va[set][0].x, va[set][0].y, va[set][0].z, va[set][0].w,
                      va[set][1].x, va[set][1].y, va[set][1].z, va[set][1].w};
        if (useAct) {
            int c = kb * 32 + pkg * 8;
            #pragma unroll
            for (int j = 0; j < 8; j++)
                a[j] = fmaxf(fmaf(a[j], g_scale[c + j], g_shift[c + j]), 0.f);
        }
        uint4 hi, lo;
        hi.x = prmt_hi(__float_as_uint(a[0]), __float_as_uint(a[1]));
        hi.y = prmt_hi(__float_as_uint(a[2]), __float_as_uint(a[3]));
        hi.z = prmt_hi(__float_as_uint(a[4]), __float_as_uint(a[5]));
        hi.w = prmt_hi(__float_as_uint(a[6]), __float_as_uint(a[7]));
        lo.x = pack_bf16_rn(a[0] - trunc_hi_f(a[0]), a[1] - trunc_hi_f(a[1]));
        lo.y = pack_bf16_rn(a[2] - trunc_hi_f(a[2]), a[3] - trunc_hi_f(a[3]));
        lo.z = pack_bf16_rn(a[4] - trunc_hi_f(a[4]), a[5] - trunc_hi_f(a[5]));
        lo.w = pack_bf16_rn(a[6] - trunc_hi_f(a[6]), a[7] - trunc_hi_f(a[7]));
        asm volatile("st.shared.v4.b32 [%0], {%1,%2,%3,%4};"
                     :: "r"(base), "r"(hi.x), "r"(hi.y), "r"(hi.z), "r"(hi.w));
        asm volatile("st.shared.v4.b32 [%0], {%1,%2,%3,%4};"
                     :: "r"(base + TILE_B), "r"(lo.x), "r"(lo.y), "r"(lo.z), "r"(lo.w));
    };

    // consumer ldmatrix offsets (within stage), precomputed
    const int aRow0 = wm * 32 + ((lane >> 3) & 1) * 8 + (lane & 7);
    const int aKh = (lane >> 4) & 1;
    const int bRow0 = wn * 32 + ((lane >> 4) & 1) * 8 + (lane & 7);
    const int bKh = (lane >> 3) & 1;
    uint32_t aOff[2][2], bOff[2][2];   // [mt|p][ks]
    #pragma unroll
    for (int mt = 0; mt < 2; mt++) {
        int row = aRow0 + mt * 16;
        #pragma unroll
        for (int ks = 0; ks < 2; ks++)
            aOff[mt][ks] = (uint32_t)(row * 64 + ((((ks << 1) + aKh) ^ ((row >> 1) & 3)) << 4));
    }
    #pragma unroll
    for (int p = 0; p < 2; p++) {
        int row = bRow0 + p * 16;
        #pragma unroll
        for (int ks = 0; ks < 2; ks++)
            bOff[p][ks] = (uint32_t)(2 * TILE_B + row * 64 + ((((ks << 1) + bKh) ^ ((row >> 1) & 3)) << 4));
    }

    // prologue: stages 0,1 in flight; A(0) stored, A(1) in regs
    cpB(0, 0);
    cpB(1, 1);
    loadG(0, 0);
    loadG(1, 1);
    storeS(0, 0, 0);
    asm volatile("cp.async.wait_group 1;");
    __syncthreads();

    for (int kb = 0; kb < 8; kb++) {
        const int st = kb % 3;
        const uint32_t stb = smb + st * STAGE3_B;
        if (kb + 2 < 8) {
            cpB((kb + 2) % 3, kb + 2);       // B for kb+2 (dist 2)
            loadG(kb + 2, kb & 1);           // A regs for kb+2 (dist 2)
        }
        if (kb + 1 < 8)
            storeS((kb + 1) % 3, (kb + 1) & 1, kb + 1);  // A smem for kb+1 (1-iter-old regs)
        #pragma unroll
        for (int ks = 0; ks < 2; ks++) {
            uint4 ah[2], al[2], bh[2], bl[2];
            #pragma unroll
            for (int mt = 0; mt < 2; mt++) {
                LDMATRIX_X4(ah[mt], stb + aOff[mt][ks]);
                LDMATRIX_X4(al[mt], stb + aOff[mt][ks] + TILE_B);
            }
            #pragma unroll
            for (int p = 0; p < 2; p++) {
                LDMATRIX_X4(bh[p], stb + bOff[p][ks]);
                LDMATRIX_X4(bl[p], stb + bOff[p][ks] + TILE_B);
            }
            #pragma unroll
            for (int mt = 0; mt < 2; mt++) {
                #pragma unroll
                for (int p = 0; p < 2; p++) {
                    MMA_BF16(acc[mt][2*p],   ah[mt], bh[p].x, bh[p].y);
                    MMA_BF16(acc[mt][2*p],   ah[mt], bl[p].x, bl[p].y);
                    MMA_BF16(acc[mt][2*p],   al[mt], bh[p].x, bh[p].y);
                    MMA_BF16(acc[mt][2*p+1], ah[mt], bh[p].z, bh[p].w);
                    MMA_BF16(acc[mt][2*p+1], ah[mt], bl[p].z, bl[p].w);
                    MMA_BF16(acc[mt][2*p+1], al[mt], bh[p].z, bh[p].w);
                }
            }
        }
        if (kb < 7) {
            if (kb < 6) { asm volatile("cp.async.wait_group 1;"); }
            else        { asm volatile("cp.async.wait_group 0;"); }
            __syncthreads();
        }
    }

    // epilogue: +bias, store, fused per-channel stats
    float sp[8], ssp[8];
    #pragma unroll
    for (int c = 0; c < 8; c++) { sp[c] = 0.f; ssp[c] = 0.f; }

    const int gId = lane >> 2, l4 = lane & 3;
    #pragma unroll
    for (int mt = 0; mt < 2; mt++) {
        size_t row0 = rowBase + wm * 32 + mt * 16 + gId;
        #pragma unroll
        for (int nt = 0; nt < 4; nt++) {
            int col0 = colBase + wn * 32 + nt * 8 + 2 * l4;
            float b0 = bias[col0], b1 = bias[col0 + 1];
            float v00 = acc[mt][nt][0] + b0, v01 = acc[mt][nt][1] + b1;
            float v10 = acc[mt][nt][2] + b0, v11 = acc[mt][nt][3] + b1;
            *(float2*)(out + row0 * O + col0)        = make_float2(v00, v01);
            *(float2*)(out + (row0 + 8) * O + col0)  = make_float2(v10, v11);
            sp[nt * 2 + 0]  += v00 + v10;
            sp[nt * 2 + 1]  += v01 + v11;
            ssp[nt * 2 + 0] += v00 * v00 + v10 * v10;
            ssp[nt * 2 + 1] += v01 * v01 + v11 * v11;
        }
    }
    #pragma unroll
    for (int c = 0; c < 8; c++) {
        #pragma unroll
        for (int mask = 4; mask <= 16; mask <<= 1) {
            sp[c]  += __shfl_xor_sync(0xffffffffu, sp[c],  mask);
            ssp[c] += __shfl_xor_sync(0xffffffffu, ssp[c], mask);
        }
    }
    if (lane < 4) {
        #pragma unroll
        for (int nt = 0; nt < 4; nt++) {
            #pragma unroll
            for (int h = 0; h < 2; h++) {
                int col = colBase + wn * 32 + nt * 8 + 2 * lane + h;
                atomicAdd(&g_sum[col],   sp[nt * 2 + h]);
                atomicAdd(&g_sumsq[col], ssp[nt * 2 + h]);
            }
        }
    }
}

// ---------------------------------------------------------------------------
// fold BN into per-channel affine: scale = gamma*rsqrt(var+eps), shift = beta - mu*scale
__global__ void bn_finalize_kernel(const float* __restrict__ g,
                                   const float* __restrict__ beta, int O) {
    int t = threadIdx.x; // 256 threads always
    if (t < O) {
        const float cnt = (float)Rr;
        float mu  = g_sum[t] / cnt;
        float var = fmaxf(g_sumsq[t] / cnt - mu * mu, 0.f);
        float sc  = rsqrtf(var + BN_EPS) * g[t];
        g_scale[t] = sc;
        g_shift[t] = beta[t] - mu * sc;
    }
    g_sum[t] = 0.f; g_sumsq[t] = 0.f;
}

// ---------------------------------------------------------------------------
// final BN+ReLU + transpose [b][n][o] -> [b][o][n] into d_out (O = 128)
__global__ void output_kernel(const float* __restrict__ in, float* __restrict__ out) {
    __shared__ float t[32][33];
    const int b = blockIdx.z;
    const int n0 = blockIdx.x * 32, o0 = blockIdx.y * 32;
    const int tx = threadIdx.x, ty = threadIdx.y; // 32 x 8
    #pragma unroll
    for (int k = 0; k < 32; k += 8) {
        int o = o0 + tx;
        float v = in[((size_t)b * Np + n0 + ty + k) * 128 + o];
        t[ty + k][tx] = fmaxf(fmaf(v, g_scale[o], g_shift[o]), 0.f);
    }
    __syncthreads();
    #pragma unroll
    for (int k = 0; k < 32; k += 8)
        out[((size_t)b * 128 + o0 + ty + k) * Np + n0 + tx] = t[tx][ty + k];
}

// ---------------------------------------------------------------------------
extern "C" void kernel_launch(void* const* d_in, const int* in_sizes, int n_in,
                              void* d_out, int out_size) {
    const float* p   = (const float*)d_in[0];
    const float* q   = (const float*)d_in[1];
    const float* x   = (const float*)d_in[2];
    const float* w0  = (const float*)d_in[3];
    const float* b0  = (const float*)d_in[4];
    const float* g0  = (const float*)d_in[5];
    const float* be0 = (const float*)d_in[6];
    const float* w1  = (const float*)d_in[7];
    const float* b1  = (const float*)d_in[8];
    const float* g1  = (const float*)d_in[9];
    const float* be1 = (const float*)d_in[10];
    const float* w2  = (const float*)d_in[11];
    const float* b2  = (const float*)d_in[12];
    const float* g2  = (const float*)d_in[13];
    const float* be2 = (const float*)d_in[14];
    float* out = (float*)d_out;

    float *bufA, *bufB, *xT;
    uint4* wcv;
    cudaGetSymbolAddress((void**)&bufA, g_bufA);
    cudaGetSymbolAddress((void**)&bufB, g_bufB);
    cudaGetSymbolAddress((void**)&xT,  g_xT);
    cudaGetSymbolAddress((void**)&wcv, g_wcv);

    const int Qfloats = Bb * Mp * 3;                    // 24576
    const int Hfloats = Bb * 128 * Np;                  // 8388608
    const int qoff = (out_size >= Qfloats + Hfloats) ? Qfloats : 0;

    cudaFuncSetAttribute(gemm_bf16x3_kernel,
                         cudaFuncAttributeMaxDynamicSharedMemorySize, SMEM_GEMM_BYTES);

    zero_stats_kernel<<<1, 256>>>();
    transpose_x_kernel<<<dim3(Mp / 32, Cc / 32, Bb), dim3(32, 8)>>>(x, xT);
    knn_interp_kernel<<<dim3(Bb, Np / 128), 128>>>(p, q, xT, bufA);

    // layer 0: in bufA (raw), out bufB (256 ch) — stats fused
    wconv_kernel<<<dim3(2, 8), 512>>>(w0, wcv);
    gemm_bf16x3_kernel<<<dim3(Rr / 128, 2), 512, SMEM_GEMM_BYTES>>>(bufA, wcv, b0, 0, bufB, 256);
    bn_finalize_kernel<<<1, 256>>>(g0, be0, 256);

    // layer 1: in bufB (BN0+ReLU fused on load), out bufA (256 ch)
    wconv_kernel<<<dim3(2, 8), 512>>>(w1, wcv);
    gemm_bf16x3_kernel<<<dim3(Rr / 128, 2), 512, SMEM_GEMM_BYTES>>>(bufB, wcv, b1, 1, bufA, 256);
    bn_finalize_kernel<<<1, 256>>>(g1, be1, 256);

    // layer 2: in bufA (BN1+ReLU fused on load), out bufB (128 ch)
    wconv_kernel<<<dim3(1, 8), 512>>>(w2, wcv);
    gemm_bf16x3_kernel<<<dim3(Rr / 128, 1), 512, SMEM_GEMM_BYTES>>>(bufA, wcv, b2, 1, bufB, 128);
    bn_finalize_kernel<<<1, 256>>>(g2, be2, 128);

    // output: [q | BN2+ReLU(h) transposed to [B,128,N]]
    if (qoff)
        cudaMemcpyAsync(out, q, (size_t)Qfloats * sizeof(float),
                        cudaMemcpyDeviceToDevice);
    output_kernel<<<dim3(Np / 32, 4, Bb), dim3(32, 8)>>>(bufB, out + qoff);
}

// round 8
// speedup vs baseline: 1.2122x; 1.2122x over previous
#include <cuda_runtime.h>
#include <cstddef>
#include <cstdint>

// Problem constants
#define Bb 8
#define Np 8192
#define Mp 1024
#define Cc 256
#define Rr (Bb*Np)       // 65536 rows
#define BN_EPS 1e-5f

// Scratch (static __device__ — no allocations allowed)
__device__ float g_bufA[(size_t)Rr*Cc];     // 64 MB
__device__ float g_bufB[(size_t)Rr*Cc];     // 64 MB
__device__ float g_xT[(size_t)Bb*Mp*Cc];    // 8 MB
__device__ float g_sum[Cc];
__device__ float g_sumsq[Cc];
__device__ float g_scale[Cc];
__device__ float g_shift[Cc];

// ---------------------------------------------------------------------------
__global__ void zero_stats_kernel() {
    int t = threadIdx.x;
    g_sum[t] = 0.f; g_sumsq[t] = 0.f;
}

// ---------------------------------------------------------------------------
// transpose x[b][c][m] -> xT[b][m][c]
__global__ void transpose_x_kernel(const float* __restrict__ x, float* __restrict__ xT) {
    __shared__ float t[32][33];
    int b = blockIdx.z;
    int m0 = blockIdx.x * 32, c0 = blockIdx.y * 32;
    int tx = threadIdx.x, ty = threadIdx.y; // 32 x 8
    const float* xb = x + (size_t)b * Cc * Mp;
    #pragma unroll
    for (int k = 0; k < 32; k += 8)
        t[ty + k][tx] = xb[(size_t)(c0 + ty + k) * Mp + m0 + tx];
    __syncthreads();
    float* ob = xT + (size_t)b * Mp * Cc;
    #pragma unroll
    for (int k = 0; k < 32; k += 8)
        ob[(size_t)(m0 + ty + k) * Cc + c0 + tx] = t[tx][ty + k];
}

// ---------------------------------------------------------------------------
// 3-NN + inverse-distance-weighted interpolation. Writes h0 in [b][n][c].
// Even/odd 2-chain top-3 scan for ILP; float4-vectorized gather.
__global__ void knn_interp_kernel(const float* __restrict__ p,
                                  const float* __restrict__ q,
                                  const float* __restrict__ xT,
                                  float* __restrict__ h0) {
    __shared__ float sqx[Mp], sqy[Mp], sqz[Mp], sqq[Mp];
    __shared__ float sw[128][3];
    __shared__ int   si[128][3];
    const int b = blockIdx.x;
    const int n0 = blockIdx.y * 128;
    const int tid = threadIdx.x;

    for (int m = tid; m < Mp; m += 128) {
        float qx = q[((size_t)b * Mp + m) * 3 + 0];
        float qy = q[((size_t)b * Mp + m) * 3 + 1];
        float qz = q[((size_t)b * Mp + m) * 3 + 2];
        sqx[m] = qx; sqy[m] = qy; sqz[m] = qz;
        sqq[m] = qx * qx + qy * qy + qz * qz;
    }
    __syncthreads();

    const int n = n0 + tid;
    float px = p[((size_t)b * Np + n) * 3 + 0];
    float py = p[((size_t)b * Np + n) * 3 + 1];
    float pz = p[((size_t)b * Np + n) * 3 + 2];
    float pp = px * px + py * py + pz * pz;

    float e0 = 3.4e38f, e1 = 3.4e38f, e2 = 3.4e38f;
    int   ei0 = 0, ei1 = 0, ei2 = 0;
    float o0 = 3.4e38f, o1 = 3.4e38f, o2 = 3.4e38f;
    int   oi0 = 0, oi1 = 0, oi2 = 0;
    #pragma unroll 2
    for (int m = 0; m < Mp; m += 2) {
        float dotE = px * sqx[m] + py * sqy[m] + pz * sqz[m];
        float dE = pp + sqq[m] - 2.f * dotE;
        float dotO = px * sqx[m+1] + py * sqy[m+1] + pz * sqz[m+1];
        float dO = pp + sqq[m+1] - 2.f * dotO;
        if (dE < e2) {
            if (dE < e1) {
                e2 = e1; ei2 = ei1;
                if (dE < e0) { e1 = e0; ei1 = ei0; e0 = dE; ei0 = m; }
                else         { e1 = dE; ei1 = m; }
            } else { e2 = dE; ei2 = m; }
        }
        if (dO < o2) {
            if (dO < o1) {
                o2 = o1; oi2 = oi1;
                if (dO < o0) { o1 = o0; oi1 = oi0; o0 = dO; oi0 = m+1; }
                else         { o1 = dO; oi1 = m+1; }
            } else { o2 = dO; oi2 = m+1; }
        }
    }
    #pragma unroll
    for (int c = 0; c < 3; c++) {
        float d = (c == 0) ? o0 : (c == 1) ? o1 : o2;
        int   i = (c == 0) ? oi0 : (c == 1) ? oi1 : oi2;
        if (d < e2) {
            if (d < e1) {
                e2 = e1; ei2 = ei1;
                if (d < e0) { e1 = e0; ei1 = ei0; e0 = d; ei0 = i; }
                else        { e1 = d; ei1 = i; }
            } else { e2 = d; ei2 = i; }
        }
    }
    float a0 = 1.f / fmaxf(e0, 1e-10f);
    float a1 = 1.f / fmaxf(e1, 1e-10f);
    float a2 = 1.f / fmaxf(e2, 1e-10f);
    float inv = 1.f / (a0 + a1 + a2);
    sw[tid][0] = a0 * inv; sw[tid][1] = a1 * inv; sw[tid][2] = a2 * inv;
    si[tid][0] = ei0; si[tid][1] = ei1; si[tid][2] = ei2;
    __syncthreads();

    const int lane = tid & 31, warp = tid >> 5;
    const float* xb = xT + (size_t)b * Mp * Cc;
    for (int nl = warp * 32; nl < warp * 32 + 32; nl++) {
        float w0 = sw[nl][0], w1 = sw[nl][1], w2 = sw[nl][2];
        const float4* r0 = (const float4*)(xb + (size_t)si[nl][0] * Cc);
        const float4* r1 = (const float4*)(xb + (size_t)si[nl][1] * Cc);
        const float4* r2 = (const float4*)(xb + (size_t)si[nl][2] * Cc);
        float4* o4 = (float4*)(h0 + ((size_t)b * Np + n0 + nl) * Cc);
        #pragma unroll
        for (int c = lane; c < Cc / 4; c += 32) {
            float4 a = r0[c], bq = r1[c], cq = r2[c];
            float4 v;
            v.x = w0 * a.x + w1 * bq.x + w2 * cq.x;
            v.y = w0 * a.y + w1 * bq.y + w2 * cq.y;
            v.z = w0 * a.z + w1 * bq.z + w2 * cq.z;
            v.w = w0 * a.w + w1 * bq.w + w2 * cq.w;
            o4[c] = v;
        }
    }
}

// ---------------------------------------------------------------------------
// bf16x3 emulated-fp32 GEMM via legacy mma.sync (sm_80 PTX path)
// ---------------------------------------------------------------------------
__device__ __forceinline__ uint32_t prmt_hi(uint32_t a, uint32_t b) {
    uint32_t r; asm("prmt.b32 %0, %1, %2, 0x7632;" : "=r"(r) : "r"(a), "r"(b));
    return r;   // {lo16 = a.hi16, hi16 = b.hi16}
}
__device__ __forceinline__ uint32_t pack_bf16_rn(float lo0, float lo1) {
    uint32_t r; asm("cvt.rn.bf16x2.f32 %0, %1, %2;" : "=r"(r) : "f"(lo1), "f"(lo0));
    return r;   // low half = lo0
}
__device__ __forceinline__ float trunc_hi_f(float f) {
    return __uint_as_float(__float_as_uint(f) & 0xFFFF0000u);
}

#define MMA_BF16(c, a, b0v, b1v) \
    asm volatile("mma.sync.aligned.m16n8k16.row.col.f32.bf16.bf16.f32 " \
        "{%0,%1,%2,%3},{%4,%5,%6,%7},{%8,%9},{%0,%1,%2,%3};" \
        : "+f"((c)[0]), "+f"((c)[1]), "+f"((c)[2]), "+f"((c)[3]) \
        : "r"((a).x), "r"((a).y), "r"((a).z), "r"((a).w), "r"(b0v), "r"(b1v))

#define LDMATRIX_X4(r, addr) \
    asm volatile("ldmatrix.sync.aligned.m8n8.x4.shared.b16 {%0,%1,%2,%3}, [%4];" \
        : "=r"((r).x), "=r"((r).y), "=r"((r).z), "=r"((r).w) : "r"(addr))

// smem tiles: bf16, row-major, 128 rows x 32 k = 64 B/row, XOR-granule swizzle.
// addr(row, kg) = row*64 + (kg ^ ((row>>1)&3))*16        (kg = 16B granule 0..3)
#define TILE_B   8192                 // one 128x32 bf16 tile
#define STAGE_B  (4 * TILE_B)         // A_hi, A_lo, B_hi, B_lo
#define SMEM_GEMM_BYTES (2 * STAGE_B) // 65536

// out[r][o] = sum_c act(A[r][c]) * W[o][c] + bias[o], K=256, tile 128x128.
// 512 threads, 16 warps (4M x 4N). Double-buffered stages (R5 structure);
// B fragments double-buffered across ks to cover LDSM latency.
// BN stats fused into epilogue.
__global__ void __launch_bounds__(512)
gemm_bf16x3_kernel(const float* __restrict__ A, const float* __restrict__ W,
                   const float* __restrict__ bias, int useAct,
                   float* __restrict__ out, int O) {
    extern __shared__ char smc[];
    const int tid = threadIdx.x;
    const int lane = tid & 31, wid = tid >> 5;
    const int wm = wid >> 2, wn = wid & 3;
    const size_t rowBase = (size_t)blockIdx.x * 128;
    const int colBase = blockIdx.y * 128;

    const uint32_t smb = (uint32_t)__cvta_generic_to_shared(smc);

    // producer mapping: row = tid>>2 (0..127), kg = tid&3 (8 k each)
    const int prow = tid >> 2;
    const int pkg = tid & 3;
    const uint32_t pOff = (uint32_t)(prow * 64 + ((pkg ^ ((prow >> 1) & 3)) << 4));
    const float* aG = A + (rowBase + prow) * 256 + pkg * 8;
    const float* wG = W + (size_t)(colBase + prow) * 256 + pkg * 8;

    float acc[2][4][4];
    #pragma unroll
    for (int i = 0; i < 2; i++)
        #pragma unroll
        for (int j = 0; j < 4; j++)
            #pragma unroll
            for (int r = 0; r < 4; r++) acc[i][j][r] = 0.f;

    float4 va0, va1, vb0, vb1;
    auto loadG = [&](int kb) {
        va0 = *(const float4*)(aG + kb * 32);
        va1 = *(const float4*)(aG + kb * 32 + 4);
        vb0 = *(const float4*)(wG + kb * 32);
        vb1 = *(const float4*)(wG + kb * 32 + 4);
    };
    auto storeS = [&](int s, int kb) {
        uint32_t base = smb + s * STAGE_B + pOff;
        float a[8] = {va0.x, va0.y, va0.z, va0.w, va1.x, va1.y, va1.z, va1.w};
        if (useAct) {
            int c = kb * 32 + pkg * 8;
            #pragma unroll
            for (int j = 0; j < 8; j++)
                a[j] = fmaxf(fmaf(a[j], g_scale[c + j], g_shift[c + j]), 0.f);
        }
        uint4 hi, lo;
        hi.x = prmt_hi(__float_as_uint(a[0]), __float_as_uint(a[1]));
        hi.y = prmt_hi(__float_as_uint(a[2]), __float_as_uint(a[3]));
        hi.z = prmt_hi(__float_as_uint(a[4]), __float_as_uint(a[5]));
        hi.w = prmt_hi(__float_as_uint(a[6]), __float_as_uint(a[7]));
        lo.x = pack_bf16_rn(a[0] - trunc_hi_f(a[0]), a[1] - trunc_hi_f(a[1]));
        lo.y = pack_bf16_rn(a[2] - trunc_hi_f(a[2]), a[3] - trunc_hi_f(a[3]));
        lo.z = pack_bf16_rn(a[4] - trunc_hi_f(a[4]), a[5] - trunc_hi_f(a[5]));
        lo.w = pack_bf16_rn(a[6] - trunc_hi_f(a[6]), a[7] - trunc_hi_f(a[7]));
        asm volatile("st.shared.v4.b32 [%0], {%1,%2,%3,%4};"
                     :: "r"(base), "r"(hi.x), "r"(hi.y), "r"(hi.z), "r"(hi.w));
        asm volatile("st.shared.v4.b32 [%0], {%1,%2,%3,%4};"
                     :: "r"(base + TILE_B), "r"(lo.x), "r"(lo.y), "r"(lo.z), "r"(lo.w));

        float b[8] = {vb0.x, vb0.y, vb0.z, vb0.w, vb1.x, vb1.y, vb1.z, vb1.w};
        hi.x = prmt_hi(__float_as_uint(b[0]), __float_as_uint(b[1]));
        hi.y = prmt_hi(__float_as_uint(b[2]), __float_as_uint(b[3]));
        hi.z = prmt_hi(__float_as_uint(b[4]), __float_as_uint(b[5]));
        hi.w = prmt_hi(__float_as_uint(b[6]), __float_as_uint(b[7]));
        lo.x = pack_bf16_rn(b[0] - trunc_hi_f(b[0]), b[1] - trunc_hi_f(b[1]));
        lo.y = pack_bf16_rn(b[2] - trunc_hi_f(b[2]), b[3] - trunc_hi_f(b[3]));
        lo.z = pack_bf16_rn(b[4] - trunc_hi_f(b[4]), b[5] - trunc_hi_f(b[5]));
        lo.w = pack_bf16_rn(b[6] - trunc_hi_f(b[6]), b[7] - trunc_hi_f(b[7]));
        asm volatile("st.shared.v4.b32 [%0], {%1,%2,%3,%4};"
                     :: "r"(base + 2 * TILE_B), "r"(hi.x), "r"(hi.y), "r"(hi.z), "r"(hi.w));
        asm volatile("st.shared.v4.b32 [%0], {%1,%2,%3,%4};"
                     :: "r"(base + 3 * TILE_B), "r"(lo.x), "r"(lo.y), "r"(lo.z), "r"(lo.w));
    };

    // consumer per-lane ldmatrix offsets, precomputed
    const int aRow0 = wm * 32 + ((lane >> 3) & 1) * 8 + (lane & 7);
    const int aKh = (lane >> 4) & 1;
    const int bRow0 = wn * 32 + ((lane >> 4) & 1) * 8 + (lane & 7);
    const int bKh = (lane >> 3) & 1;
    uint32_t aOff[2][2], bOff[2][2];   // [mt|p][ks]
    #pragma unroll
    for (int mt = 0; mt < 2; mt++) {
        int row = aRow0 + mt * 16;
        #pragma unroll
        for (int ks = 0; ks < 2; ks++)
            aOff[mt][ks] = (uint32_t)(row * 64 + ((((ks << 1) + aKh) ^ ((row >> 1) & 3)) << 4));
    }
    #pragma unroll
    for (int p = 0; p < 2; p++) {
        int row = bRow0 + p * 16;
        #pragma unroll
        for (int ks = 0; ks < 2; ks++)
            bOff[p][ks] = (uint32_t)(2 * TILE_B + row * 64 + ((((ks << 1) + bKh) ^ ((row >> 1) & 3)) << 4));
    }

    loadG(0);
    storeS(0, 0);
    __syncthreads();

    for (int kb = 0; kb < 8; kb++) {
        const int s = kb & 1;
        const uint32_t stA = smb + s * STAGE_B;
        if (kb < 7) loadG(kb + 1);

        uint4 ah[2], al[2], bh[2][2], bl[2][2];
        // ks0: A + B fragments
        #pragma unroll
        for (int mt = 0; mt < 2; mt++) {
            LDMATRIX_X4(ah[mt], stA + aOff[mt][0]);
            LDMATRIX_X4(al[mt], stA + aOff[mt][0] + TILE_B);
        }
        #pragma unroll
        for (int p = 0; p < 2; p++) {
            LDMATRIX_X4(bh[0][p], stA + bOff[p][0]);
            LDMATRIX_X4(bl[0][p], stA + bOff[p][0] + TILE_B);
        }
        // prefetch ks1 B fragments (covers LDSM latency behind MMA ks0)
        #pragma unroll
        for (int p = 0; p < 2; p++) {
            LDMATRIX_X4(bh[1][p], stA + bOff[p][1]);
            LDMATRIX_X4(bl[1][p], stA + bOff[p][1] + TILE_B);
        }
        // MMA ks0
        #pragma unroll
        for (int mt = 0; mt < 2; mt++) {
            #pragma unroll
            for (int p = 0; p < 2; p++) {
                MMA_BF16(acc[mt][2*p],   ah[mt], bh[0][p].x, bh[0][p].y);
                MMA_BF16(acc[mt][2*p],   ah[mt], bl[0][p].x, bl[0][p].y);
                MMA_BF16(acc[mt][2*p],   al[mt], bh[0][p].x, bh[0][p].y);
                MMA_BF16(acc[mt][2*p+1], ah[mt], bh[0][p].z, bh[0][p].w);
                MMA_BF16(acc[mt][2*p+1], ah[mt], bl[0][p].z, bl[0][p].w);
                MMA_BF16(acc[mt][2*p+1], al[mt], bh[0][p].z, bh[0][p].w);
            }
        }
        // ks1 A fragments (WAR on ah/al clears after ks0's first MMAs)
        #pragma unroll
        for (int mt = 0; mt < 2; mt++) {
            LDMATRIX_X4(ah[mt], stA + aOff[mt][1]);
            LDMATRIX_X4(al[mt], stA + aOff[mt][1] + TILE_B);
        }
        // MMA ks1
        #pragma unroll
        for (int mt = 0; mt < 2; mt++) {
            #pragma unroll
            for (int p = 0; p < 2; p++) {
                MMA_BF16(acc[mt][2*p],   ah[mt], bh[1][p].x, bh[1][p].y);
                MMA_BF16(acc[mt][2*p],   ah[mt], bl[1][p].x, bl[1][p].y);
                MMA_BF16(acc[mt][2*p],   al[mt], bh[1][p].x, bh[1][p].y);
                MMA_BF16(acc[mt][2*p+1], ah[mt], bh[1][p].z, bh[1][p].w);
                MMA_BF16(acc[mt][2*p+1], ah[mt], bl[1][p].z, bl[1][p].w);
                MMA_BF16(acc[mt][2*p+1], al[mt], bh[1][p].z, bh[1][p].w);
            }
        }

        if (kb < 7) {
            storeS(s ^ 1, kb + 1);
            __syncthreads();
        }
    }

    // epilogue: +bias, store, fused per-channel stats
    float sp[8], ssp[8];
    #pragma unroll
    for (int c = 0; c < 8; c++) { sp[c] = 0.f; ssp[c] = 0.f; }

    const int gId = lane >> 2, l4 = lane & 3;
    #pragma unroll
    for (int mt = 0; mt < 2; mt++) {
        size_t row0 = rowBase + wm * 32 + mt * 16 + gId;
        #pragma unroll
        for (int nt = 0; nt < 4; nt++) {
            int col0 = colBase + wn * 32 + nt * 8 + 2 * l4;
            float b0 = bias[col0], b1 = bias[col0 + 1];
            float v00 = acc[mt][nt][0] + b0, v01 = acc[mt][nt][1] + b1;
            float v10 = acc[mt][nt][2] + b0, v11 = acc[mt][nt][3] + b1;
            *(float2*)(out + row0 * O + col0)        = make_float2(v00, v01);
            *(float2*)(out + (row0 + 8) * O + col0)  = make_float2(v10, v11);
            sp[nt * 2 + 0]  += v00 + v10;
            sp[nt * 2 + 1]  += v01 + v11;
            ssp[nt * 2 + 0] += v00 * v00 + v10 * v10;
            ssp[nt * 2 + 1] += v01 * v01 + v11 * v11;
        }
    }
    #pragma unroll
    for (int c = 0; c < 8; c++) {
        #pragma unroll
        for (int mask = 4; mask <= 16; mask <<= 1) {
            sp[c]  += __shfl_xor_sync(0xffffffffu, sp[c],  mask);
            ssp[c] += __shfl_xor_sync(0xffffffffu, ssp[c], mask);
        }
    }
    if (lane < 4) {
        #pragma unroll
        for (int nt = 0; nt < 4; nt++) {
            #pragma unroll
            for (int h = 0; h < 2; h++) {
                int col = colBase + wn * 32 + nt * 8 + 2 * lane + h;
                atomicAdd(&g_sum[col],   sp[nt * 2 + h]);
                atomicAdd(&g_sumsq[col], ssp[nt * 2 + h]);
            }
        }
    }
}

// ---------------------------------------------------------------------------
// fold BN into per-channel affine: scale = gamma*rsqrt(var+eps), shift = beta - mu*scale
__global__ void bn_finalize_kernel(const float* __restrict__ g,
                                   const float* __restrict__ beta, int O) {
    int t = threadIdx.x; // 256 threads always
    if (t < O) {
        const float cnt = (float)Rr;
        float mu  = g_sum[t] / cnt;
        float var = fmaxf(g_sumsq[t] / cnt - mu * mu, 0.f);
        float sc  = rsqrtf(var + BN_EPS) * g[t];
        g_scale[t] = sc;
        g_shift[t] = beta[t] - mu * sc;
    }
    g_sum[t] = 0.f; g_sumsq[t] = 0.f;
}

// ---------------------------------------------------------------------------
// final BN+ReLU + transpose [b][n][o] -> [b][o][n] into d_out (O = 128)
__global__ void output_kernel(const float* __restrict__ in, float* __restrict__ out) {
    __shared__ float t[32][33];
    const int b = blockIdx.z;
    const int n0 = blockIdx.x * 32, o0 = blockIdx.y * 32;
    const int tx = threadIdx.x, ty = threadIdx.y; // 32 x 8
    #pragma unroll
    for (int k = 0; k < 32; k += 8) {
        int o = o0 + tx;
        float v = in[((size_t)b * Np + n0 + ty + k) * 128 + o];
        t[ty + k][tx] = fmaxf(fmaf(v, g_scale[o], g_shift[o]), 0.f);
    }
    __syncthreads();
    #pragma unroll
    for (int k = 0; k < 32; k += 8)
        out[((size_t)b * 128 + o0 + ty + k) * Np + n0 + tx] = t[tx][ty + k];
}

// ---------------------------------------------------------------------------
extern "C" void kernel_launch(void* const* d_in, const int* in_sizes, int n_in,
                              void* d_out, int out_size) {
    const float* p   = (const float*)d_in[0];
    const float* q   = (const float*)d_in[1];
    const float* x   = (const float*)d_in[2];
    const float* w0  = (const float*)d_in[3];
    const float* b0  = (const float*)d_in[4];
    const float* g0  = (const float*)d_in[5];
    const float* be0 = (const float*)d_in[6];
    const float* w1  = (const float*)d_in[7];
    const float* b1  = (const float*)d_in[8];
    const float* g1  = (const float*)d_in[9];
    const float* be1 = (const float*)d_in[10];
    const float* w2  = (const float*)d_in[11];
    const float* b2  = (const float*)d_in[12];
    const float* g2  = (const float*)d_in[13];
    const float* be2 = (const float*)d_in[14];
    float* out = (float*)d_out;

    float *bufA, *bufB, *xT;
    cudaGetSymbolAddress((void**)&bufA, g_bufA);
    cudaGetSymbolAddress((void**)&bufB, g_bufB);
    cudaGetSymbolAddress((void**)&xT,  g_xT);

    const int Qfloats = Bb * Mp * 3;                    // 24576
    const int Hfloats = Bb * 128 * Np;                  // 8388608
    const int qoff = (out_size >= Qfloats + Hfloats) ? Qfloats : 0;

    cudaFuncSetAttribute(gemm_bf16x3_kernel,
                         cudaFuncAttributeMaxDynamicSharedMemorySize, SMEM_GEMM_BYTES);

    zero_stats_kernel<<<1, 256>>>();
    transpose_x_kernel<<<dim3(Mp / 32, Cc / 32, Bb), dim3(32, 8)>>>(x, xT);
    knn_interp_kernel<<<dim3(Bb, Np / 128), 128>>>(p, q, xT, bufA);

    // layer 0: in bufA (raw), out bufB (256 ch) — stats fused
    gemm_bf16x3_kernel<<<dim3(Rr / 128, 2), 512, SMEM_GEMM_BYTES>>>(bufA, w0, b0, 0, bufB, 256);
    bn_finalize_kernel<<<1, 256>>>(g0, be0, 256);

    // layer 1: in bufB (BN0+ReLU fused on load), out bufA (256 ch)
    gemm_bf16x3_kernel<<<dim3(Rr / 128, 2), 512, SMEM_GEMM_BYTES>>>(bufB, w1, b1, 1, bufA, 256);
    bn_finalize_kernel<<<1, 256>>>(g1, be1, 256);

    // layer 2: in bufA (BN1+ReLU fused on load), out bufB (128 ch)
    gemm_bf16x3_kernel<<<dim3(Rr / 128, 1), 512, SMEM_GEMM_BYTES>>>(bufA, w2, b2, 1, bufB, 128);
    bn_finalize_kernel<<<1, 256>>>(g2, be2, 128);

    // output: [q | BN2+ReLU(h) transposed to [B,128,N]]
    if (qoff)
        cudaMemcpyAsync(out, q, (size_t)Qfloats * sizeof(float),
                        cudaMemcpyDeviceToDevice);
    output_kernel<<<dim3(Np / 32, 4, Bb), dim3(32, 8)>>>(bufB, out + qoff);
}

// round 9
// speedup vs baseline: 1.2699x; 1.0476x over previous
#include <cuda_runtime.h>
#include <cstddef>
#include <cstdint>

// Problem constants
#define Bb 8
#define Np 8192
#define Mp 1024
#define Cc 256
#define Rr (Bb*Np)       // 65536 rows
#define BN_EPS 1e-5f

// Scratch (static __device__ — no allocations allowed)
__device__ float g_bufA[(size_t)Rr*Cc];     // 64 MB
__device__ float g_bufB[(size_t)Rr*Cc];     // 64 MB
__device__ float g_xT[(size_t)Bb*Mp*Cc];    // 8 MB
__device__ float g_sum[Cc];
__device__ float g_sumsq[Cc];
__device__ float g_scale[Cc];
__device__ float g_shift[Cc];

// ---------------------------------------------------------------------------
__global__ void zero_stats_kernel() {
    int t = threadIdx.x;
    g_sum[t] = 0.f; g_sumsq[t] = 0.f;
}

// ---------------------------------------------------------------------------
// transpose x[b][c][m] -> xT[b][m][c]
__global__ void transpose_x_kernel(const float* __restrict__ x, float* __restrict__ xT) {
    __shared__ float t[32][33];
    int b = blockIdx.z;
    int m0 = blockIdx.x * 32, c0 = blockIdx.y * 32;
    int tx = threadIdx.x, ty = threadIdx.y; // 32 x 8
    const float* xb = x + (size_t)b * Cc * Mp;
    #pragma unroll
    for (int k = 0; k < 32; k += 8)
        t[ty + k][tx] = xb[(size_t)(c0 + ty + k) * Mp + m0 + tx];
    __syncthreads();
    float* ob = xT + (size_t)b * Mp * Cc;
    #pragma unroll
    for (int k = 0; k < 32; k += 8)
        ob[(size_t)(m0 + ty + k) * Cc + c0 + tx] = t[tx][ty + k];
}

// ---------------------------------------------------------------------------
// 3-NN + inverse-distance-weighted interpolation. Writes h0 in [b][n][c].
// Even/odd 2-chain top-3 scan for ILP; float4-vectorized gather.
__global__ void knn_interp_kernel(const float* __restrict__ p,
                                  const float* __restrict__ q,
                                  const float* __restrict__ xT,
                                  float* __restrict__ h0) {
    __shared__ float sqx[Mp], sqy[Mp], sqz[Mp], sqq[Mp];
    __shared__ float sw[128][3];
    __shared__ int   si[128][3];
    const int b = blockIdx.x;
    const int n0 = blockIdx.y * 128;
    const int tid = threadIdx.x;

    for (int m = tid; m < Mp; m += 128) {
        float qx = q[((size_t)b * Mp + m) * 3 + 0];
        float qy = q[((size_t)b * Mp + m) * 3 + 1];
        float qz = q[((size_t)b * Mp + m) * 3 + 2];
        sqx[m] = qx; sqy[m] = qy; sqz[m] = qz;
        sqq[m] = qx * qx + qy * qy + qz * qz;
    }
    __syncthreads();

    const int n = n0 + tid;
    float px = p[((size_t)b * Np + n) * 3 + 0];
    float py = p[((size_t)b * Np + n) * 3 + 1];
    float pz = p[((size_t)b * Np + n) * 3 + 2];
    float pp = px * px + py * py + pz * pz;

    float e0 = 3.4e38f, e1 = 3.4e38f, e2 = 3.4e38f;
    int   ei0 = 0, ei1 = 0, ei2 = 0;
    float o0 = 3.4e38f, o1 = 3.4e38f, o2 = 3.4e38f;
    int   oi0 = 0, oi1 = 0, oi2 = 0;
    #pragma unroll 2
    for (int m = 0; m < Mp; m += 2) {
        float dotE = px * sqx[m] + py * sqy[m] + pz * sqz[m];
        float dE = pp + sqq[m] - 2.f * dotE;
        float dotO = px * sqx[m+1] + py * sqy[m+1] + pz * sqz[m+1];
        float dO = pp + sqq[m+1] - 2.f * dotO;
        if (dE < e2) {
            if (dE < e1) {
                e2 = e1; ei2 = ei1;
                if (dE < e0) { e1 = e0; ei1 = ei0; e0 = dE; ei0 = m; }
                else         { e1 = dE; ei1 = m; }
            } else { e2 = dE; ei2 = m; }
        }
        if (dO < o2) {
            if (dO < o1) {
                o2 = o1; oi2 = oi1;
                if (dO < o0) { o1 = o0; oi1 = oi0; o0 = dO; oi0 = m+1; }
                else         { o1 = dO; oi1 = m+1; }
            } else { o2 = dO; oi2 = m+1; }
        }
    }
    #pragma unroll
    for (int c = 0; c < 3; c++) {
        float d = (c == 0) ? o0 : (c == 1) ? o1 : o2;
        int   i = (c == 0) ? oi0 : (c == 1) ? oi1 : oi2;
        if (d < e2) {
            if (d < e1) {
                e2 = e1; ei2 = ei1;
                if (d < e0) { e1 = e0; ei1 = ei0; e0 = d; ei0 = i; }
                else        { e1 = d; ei1 = i; }
            } else { e2 = d; ei2 = i; }
        }
    }
    float a0 = 1.f / fmaxf(e0, 1e-10f);
    float a1 = 1.f / fmaxf(e1, 1e-10f);
    float a2 = 1.f / fmaxf(e2, 1e-10f);
    float inv = 1.f / (a0 + a1 + a2);
    sw[tid][0] = a0 * inv; sw[tid][1] = a1 * inv; sw[tid][2] = a2 * inv;
    si[tid][0] = ei0; si[tid][1] = ei1; si[tid][2] = ei2;
    __syncthreads();

    const int lane = tid & 31, warp = tid >> 5;
    const float* xb = xT + (size_t)b * Mp * Cc;
    for (int nl = warp * 32; nl < warp * 32 + 32; nl++) {
        float w0 = sw[nl][0], w1 = sw[nl][1], w2 = sw[nl][2];
        const float4* r0 = (const float4*)(xb + (size_t)si[nl][0] * Cc);
        const float4* r1 = (const float4*)(xb + (size_t)si[nl][1] * Cc);
        const float4* r2 = (const float4*)(xb + (size_t)si[nl][2] * Cc);
        float4* o4 = (float4*)(h0 + ((size_t)b * Np + n0 + nl) * Cc);
        #pragma unroll
        for (int c = lane; c < Cc / 4; c += 32) {
            float4 a = r0[c], bq = r1[c], cq = r2[c];
            float4 v;
            v.x = w0 * a.x + w1 * bq.x + w2 * cq.x;
            v.y = w0 * a.y + w1 * bq.y + w2 * cq.y;
            v.z = w0 * a.z + w1 * bq.z + w2 * cq.z;
            v.w = w0 * a.w + w1 * bq.w + w2 * cq.w;
            o4[c] = v;
        }
    }
}

// ---------------------------------------------------------------------------
// bf16x3 emulated-fp32 GEMM via legacy mma.sync (sm_80 PTX path)
// ---------------------------------------------------------------------------
__device__ __forceinline__ uint32_t prmt_hi(uint32_t a, uint32_t b) {
    uint32_t r; asm("prmt.b32 %0, %1, %2, 0x7632;" : "=r"(r) : "r"(a), "r"(b));
    return r;   // {lo16 = a.hi16, hi16 = b.hi16}
}
__device__ __forceinline__ uint32_t pack_bf16_rn(float lo0, float lo1) {
    uint32_t r; asm("cvt.rn.bf16x2.f32 %0, %1, %2;" : "=r"(r) : "f"(lo1), "f"(lo0));
    return r;   // low half = lo0
}
__device__ __forceinline__ float trunc_hi_f(float f) {
    return __uint_as_float(__float_as_uint(f) & 0xFFFF0000u);
}

#define MMA_BF16(c, a, b0v, b1v) \
    asm volatile("mma.sync.aligned.m16n8k16.row.col.f32.bf16.bf16.f32 " \
        "{%0,%1,%2,%3},{%4,%5,%6,%7},{%8,%9},{%0,%1,%2,%3};" \
        : "+f"((c)[0]), "+f"((c)[1]), "+f"((c)[2]), "+f"((c)[3]) \
        : "r"((a).x), "r"((a).y), "r"((a).z), "r"((a).w), "r"(b0v), "r"(b1v))

#define LDMATRIX_X4(r, addr) \
    asm volatile("ldmatrix.sync.aligned.m8n8.x4.shared.b16 {%0,%1,%2,%3}, [%4];" \
        : "=r"((r).x), "=r"((r).y), "=r"((r).z), "=r"((r).w) : "r"(addr))

// smem tiles: bf16, row-major, rows x 32 k = 64 B/row, XOR-granule swizzle.
// addr(row, kg) = row*64 + (kg ^ ((row>>1)&3))*16        (kg = 16B granule 0..3)
// Stage layout: A_hi(4K) A_lo(4K) B_hi(8K) B_lo(8K) = 24 KB; 2 stages = 48 KB.
#define A_TILE   4096                 // 64 rows x 64 B
#define B_TILE   8192                 // 128 rows x 64 B
#define STAGE_B  (2 * A_TILE + 2 * B_TILE)   // 24576
#define SMEM_GEMM_BYTES (2 * STAGE_B)        // 49152

// out[r][o] = sum_c act(A[r][c]) * W[o][c] + bias[o], K=256, CTA tile 64x128.
// 256 threads, 8 warps (2M x 4N) -> 2 CTAs/SM co-resident (decoupled barriers).
// B fragments double-buffered across ks. BN stats fused into epilogue.
__global__ void __launch_bounds__(256, 2)
gemm_bf16x3_kernel(const float* __restrict__ A, const float* __restrict__ W,
                   const float* __restrict__ bias, int useAct,
                   float* __restrict__ out, int O) {
    extern __shared__ char smc[];
    const int tid = threadIdx.x;
    const int lane = tid & 31, wid = tid >> 5;
    const int wm = wid >> 2, wn = wid & 3;           // 2M x 4N
    const size_t rowBase = (size_t)blockIdx.x * 64;
    const int colBase = blockIdx.y * 128;

    const uint32_t smb = (uint32_t)__cvta_generic_to_shared(smc);

    // producer mapping: prow = tid>>2 (0..63), pkg = tid&3 (8 k each)
    const int prow = tid >> 2;
    const int pkg = tid & 3;
    const uint32_t swz = (uint32_t)((pkg ^ ((prow >> 1) & 3)) << 4);
    const uint32_t aSlot  = (uint32_t)(prow * 64) + swz;              // A row prow
    const uint32_t bSlot0 = (uint32_t)(prow * 64) + swz;              // B row prow
    const uint32_t bSlot1 = (uint32_t)((prow + 64) * 64) +
                            (uint32_t)((pkg ^ (((prow + 64) >> 1) & 3)) << 4); // B row prow+64
    const float* aG = A + (rowBase + prow) * 256 + pkg * 8;
    const float* wG0 = W + (size_t)(colBase + prow) * 256 + pkg * 8;
    const float* wG1 = W + (size_t)(colBase + prow + 64) * 256 + pkg * 8;

    float acc[2][4][4];
    #pragma unroll
    for (int i = 0; i < 2; i++)
        #pragma unroll
        for (int j = 0; j < 4; j++)
            #pragma unroll
            for (int r = 0; r < 4; r++) acc[i][j][r] = 0.f;

    float4 va0, va1, vb0, vb1, vb2, vb3;
    auto loadG = [&](int kb) {
        va0 = *(const float4*)(aG + kb * 32);
        va1 = *(const float4*)(aG + kb * 32 + 4);
        vb0 = *(const float4*)(wG0 + kb * 32);
        vb1 = *(const float4*)(wG0 + kb * 32 + 4);
        vb2 = *(const float4*)(wG1 + kb * 32);
        vb3 = *(const float4*)(wG1 + kb * 32 + 4);
    };
    auto cvt8 = [&](const float* a, uint4& hi, uint4& lo) {
        hi.x = prmt_hi(__float_as_uint(a[0]), __float_as_uint(a[1]));
        hi.y = prmt_hi(__float_as_uint(a[2]), __float_as_uint(a[3]));
        hi.z = prmt_hi(__float_as_uint(a[4]), __float_as_uint(a[5]));
        hi.w = prmt_hi(__float_as_uint(a[6]), __float_as_uint(a[7]));
        lo.x = pack_bf16_rn(a[0] - trunc_hi_f(a[0]), a[1] - trunc_hi_f(a[1]));
        lo.y = pack_bf16_rn(a[2] - trunc_hi_f(a[2]), a[3] - trunc_hi_f(a[3]));
        lo.z = pack_bf16_rn(a[4] - trunc_hi_f(a[4]), a[5] - trunc_hi_f(a[5]));
        lo.w = pack_bf16_rn(a[6] - trunc_hi_f(a[6]), a[7] - trunc_hi_f(a[7]));
    };
    auto storeS = [&](int s, int kb) {
        const uint32_t stg = smb + s * STAGE_B;
        float a[8] = {va0.x, va0.y, va0.z, va0.w, va1.x, va1.y, va1.z, va1.w};
        if (useAct) {
            int c = kb * 32 + pkg * 8;
            #pragma unroll
            for (int j = 0; j < 8; j++)
                a[j] = fmaxf(fmaf(a[j], g_scale[c + j], g_shift[c + j]), 0.f);
        }
        uint4 hi, lo;
        cvt8(a, hi, lo);
        asm volatile("st.shared.v4.b32 [%0], {%1,%2,%3,%4};"
                     :: "r"(stg + aSlot), "r"(hi.x), "r"(hi.y), "r"(hi.z), "r"(hi.w));
        asm volatile("st.shared.v4.b32 [%0], {%1,%2,%3,%4};"
                     :: "r"(stg + A_TILE + aSlot), "r"(lo.x), "r"(lo.y), "r"(lo.z), "r"(lo.w));

        float b0a[8] = {vb0.x, vb0.y, vb0.z, vb0.w, vb1.x, vb1.y, vb1.z, vb1.w};
        cvt8(b0a, hi, lo);
        asm volatile("st.shared.v4.b32 [%0], {%1,%2,%3,%4};"
                     :: "r"(stg + 2 * A_TILE + bSlot0), "r"(hi.x), "r"(hi.y), "r"(hi.z), "r"(hi.w));
        asm volatile("st.shared.v4.b32 [%0], {%1,%2,%3,%4};"
                     :: "r"(stg + 2 * A_TILE + B_TILE + bSlot0), "r"(lo.x), "r"(lo.y), "r"(lo.z), "r"(lo.w));

        float b1a[8] = {vb2.x, vb2.y, vb2.z, vb2.w, vb3.x, vb3.y, vb3.z, vb3.w};
        cvt8(b1a, hi, lo);
        asm volatile("st.shared.v4.b32 [%0], {%1,%2,%3,%4};"
                     :: "r"(stg + 2 * A_TILE + bSlot1), "r"(hi.x), "r"(hi.y), "r"(hi.z), "r"(hi.w));
        asm volatile("st.shared.v4.b32 [%0], {%1,%2,%3,%4};"
                     :: "r"(stg + 2 * A_TILE + B_TILE + bSlot1), "r"(lo.x), "r"(lo.y), "r"(lo.z), "r"(lo.w));
    };

    // consumer per-lane ldmatrix offsets (within stage), precomputed
    const int aRow0 = wm * 32 + ((lane >> 3) & 1) * 8 + (lane & 7);
    const int aKh = (lane >> 4) & 1;
    const int bRow0 = wn * 32 + ((lane >> 4) & 1) * 8 + (lane & 7);
    const int bKh = (lane >> 3) & 1;
    uint32_t aOff[2][2], bOff[2][2];   // [mt|p][ks]
    #pragma unroll
    for (int mt = 0; mt < 2; mt++) {
        int row = aRow0 + mt * 16;
        #pragma unroll
        for (int ks = 0; ks < 2; ks++)
            aOff[mt][ks] = (uint32_t)(row * 64 + ((((ks << 1) + aKh) ^ ((row >> 1) & 3)) << 4));
    }
    #pragma unroll
    for (int p = 0; p < 2; p++) {
        int row = bRow0 + p * 16;
        #pragma unroll
        for (int ks = 0; ks < 2; ks++)
            bOff[p][ks] = (uint32_t)(2 * A_TILE + row * 64 + ((((ks << 1) + bKh) ^ ((row >> 1) & 3)) << 4));
    }

    loadG(0);
    storeS(0, 0);
    __syncthreads();

    for (int kb = 0; kb < 8; kb++) {
        const int s = kb & 1;
        const uint32_t stg = smb + s * STAGE_B;
        if (kb < 7) loadG(kb + 1);

        uint4 ah[2], al[2], bh[2][2], bl[2][2];
        #pragma unroll
        for (int mt = 0; mt < 2; mt++) {
            LDMATRIX_X4(ah[mt], stg + aOff[mt][0]);
            LDMATRIX_X4(al[mt], stg + aOff[mt][0] + A_TILE);
        }
        #pragma unroll
        for (int p = 0; p < 2; p++) {
            LDMATRIX_X4(bh[0][p], stg + bOff[p][0]);
            LDMATRIX_X4(bl[0][p], stg + bOff[p][0] + B_TILE);
        }
        #pragma unroll
        for (int p = 0; p < 2; p++) {
            LDMATRIX_X4(bh[1][p], stg + bOff[p][1]);
            LDMATRIX_X4(bl[1][p], stg + bOff[p][1] + B_TILE);
        }
        #pragma unroll
        for (int mt = 0; mt < 2; mt++) {
            #pragma unroll
            for (int p = 0; p < 2; p++) {
                MMA_BF16(acc[mt][2*p],   ah[mt], bh[0][p].x, bh[0][p].y);
                MMA_BF16(acc[mt][2*p],   ah[mt], bl[0][p].x, bl[0][p].y);
                MMA_BF16(acc[mt][2*p],   al[mt], bh[0][p].x, bh[0][p].y);
                MMA_BF16(acc[mt][2*p+1], ah[mt], bh[0][p].z, bh[0][p].w);
                MMA_BF16(acc[mt][2*p+1], ah[mt], bl[0][p].z, bl[0][p].w);
                MMA_BF16(acc[mt][2*p+1], al[mt], bh[0][p].z, bh[0][p].w);
            }
        }
        #pragma unroll
        for (int mt = 0; mt < 2; mt++) {
            LDMATRIX_X4(ah[mt], stg + aOff[mt][1]);
            LDMATRIX_X4(al[mt], stg + aOff[mt][1] + A_TILE);
        }
        #pragma unroll
        for (int mt = 0; mt < 2; mt++) {
            #pragma unroll
            for (int p = 0; p < 2; p++) {
                MMA_BF16(acc[mt][2*p],   ah[mt], bh[1][p].x, bh[1][p].y);
                MMA_BF16(acc[mt][2*p],   ah[mt], bl[1][p].x, bl[1][p].y);
                MMA_BF16(acc[mt][2*p],   al[mt], bh[1][p].x, bh[1][p].y);
                MMA_BF16(acc[mt][2*p+1], ah[mt], bh[1][p].z, bh[1][p].w);
                MMA_BF16(acc[mt][2*p+1], ah[mt], bl[1][p].z, bl[1][p].w);
                MMA_BF16(acc[mt][2*p+1], al[mt], bh[1][p].z, bh[1][p].w);
            }
        }

        if (kb < 7) {
            storeS(s ^ 1, kb + 1);
            __syncthreads();
        }
    }

    // epilogue: +bias, store, fused per-channel stats
    float sp[8], ssp[8];
    #pragma unroll
    for (int c = 0; c < 8; c++) { sp[c] = 0.f; ssp[c] = 0.f; }

    const int gId = lane >> 2, l4 = lane & 3;
    #pragma unroll
    for (int mt = 0; mt < 2; mt++) {
        size_t row0 = rowBase + wm * 32 + mt * 16 + gId;
        #pragma unroll
        for (int nt = 0; nt < 4; nt++) {
            int col0 = colBase + wn * 32 + nt * 8 + 2 * l4;
            float b0 = bias[col0], b1 = bias[col0 + 1];
            float v00 = acc[mt][nt][0] + b0, v01 = acc[mt][nt][1] + b1;
            float v10 = acc[mt][nt][2] + b0, v11 = acc[mt][nt][3] + b1;
            *(float2*)(out + row0 * O + col0)        = make_float2(v00, v01);
            *(float2*)(out + (row0 + 8) * O + col0)  = make_float2(v10, v11);
            sp[nt * 2 + 0]  += v00 + v10;
            sp[nt * 2 + 1]  += v01 + v11;
            ssp[nt * 2 + 0] += v00 * v00 + v10 * v10;
            ssp[nt * 2 + 1] += v01 * v01 + v11 * v11;
        }
    }
    #pragma unroll
    for (int c = 0; c < 8; c++) {
        #pragma unroll
        for (int mask = 4; mask <= 16; mask <<= 1) {
            sp[c]  += __shfl_xor_sync(0xffffffffu, sp[c],  mask);
            ssp[c] += __shfl_xor_sync(0xffffffffu, ssp[c], mask);
        }
    }
    if (lane < 4) {
        #pragma unroll
        for (int nt = 0; nt < 4; nt++) {
            #pragma unroll
            for (int h = 0; h < 2; h++) {
                int col = colBase + wn * 32 + nt * 8 + 2 * lane + h;
                atomicAdd(&g_sum[col],   sp[nt * 2 + h]);
                atomicAdd(&g_sumsq[col], ssp[nt * 2 + h]);
            }
        }
    }
}

// ---------------------------------------------------------------------------
// fold BN into per-channel affine: scale = gamma*rsqrt(var+eps), shift = beta - mu*scale
__global__ void bn_finalize_kernel(const float* __restrict__ g,
                                   const float* __restrict__ beta, int O) {
    int t = threadIdx.x; // 256 threads always
    if (t < O) {
        const float cnt = (float)Rr;
        float mu  = g_sum[t] / cnt;
        float var = fmaxf(g_sumsq[t] / cnt - mu * mu, 0.f);
        float sc  = rsqrtf(var + BN_EPS) * g[t];
        g_scale[t] = sc;
        g_shift[t] = beta[t] - mu * sc;
    }
    g_sum[t] = 0.f; g_sumsq[t] = 0.f;
}

// ---------------------------------------------------------------------------
// final BN+ReLU + transpose [b][n][o] -> [b][o][n] into d_out (O = 128)
__global__ void output_kernel(const float* __restrict__ in, float* __restrict__ out) {
    __shared__ float t[32][33];
    const int b = blockIdx.z;
    const int n0 = blockIdx.x * 32, o0 = blockIdx.y * 32;
    const int tx = threadIdx.x, ty = threadIdx.y; // 32 x 8
    #pragma unroll
    for (int k = 0; k < 32; k += 8) {
        int o = o0 + tx;
        float v = in[((size_t)b * Np + n0 + ty + k) * 128 + o];
        t[ty + k][tx] = fmaxf(fmaf(v, g_scale[o], g_shift[o]), 0.f);
    }
    __syncthreads();
    #pragma unroll
    for (int k = 0; k < 32; k += 8)
        out[((size_t)b * 128 + o0 + ty + k) * Np + n0 + tx] = t[tx][ty + k];
}

// ---------------------------------------------------------------------------
extern "C" void kernel_launch(void* const* d_in, const int* in_sizes, int n_in,
                              void* d_out, int out_size) {
    const float* p   = (const float*)d_in[0];
    const float* q   = (const float*)d_in[1];
    const float* x   = (const float*)d_in[2];
    const float* w0  = (const float*)d_in[3];
    const float* b0  = (const float*)d_in[4];
    const float* g0  = (const float*)d_in[5];
    const float* be0 = (const float*)d_in[6];
    const float* w1  = (const float*)d_in[7];
    const float* b1  = (const float*)d_in[8];
    const float* g1  = (const float*)d_in[9];
    const float* be1 = (const float*)d_in[10];
    const float* w2  = (const float*)d_in[11];
    const float* b2  = (const float*)d_in[12];
    const float* g2  = (const float*)d_in[13];
    const float* be2 = (const float*)d_in[14];
    float* out = (float*)d_out;

    float *bufA, *bufB, *xT;
    cudaGetSymbolAddress((void**)&bufA, g_bufA);
    cudaGetSymbolAddress((void**)&bufB, g_bufB);
    cudaGetSymbolAddress((void**)&xT,  g_xT);

    const int Qfloats = Bb * Mp * 3;                    // 24576
    const int Hfloats = Bb * 128 * Np;                  // 8388608
    const int qoff = (out_size >= Qfloats + Hfloats) ? Qfloats : 0;

    cudaFuncSetAttribute(gemm_bf16x3_kernel,
                         cudaFuncAttributeMaxDynamicSharedMemorySize, SMEM_GEMM_BYTES);

    zero_stats_kernel<<<1, 256>>>();
    transpose_x_kernel<<<dim3(Mp / 32, Cc / 32, Bb), dim3(32, 8)>>>(x, xT);
    knn_interp_kernel<<<dim3(Bb, Np / 128), 128>>>(p, q, xT, bufA);

    // layer 0: in bufA (raw), out bufB (256 ch) — stats fused
    gemm_bf16x3_kernel<<<dim3(Rr / 64, 2), 256, SMEM_GEMM_BYTES>>>(bufA, w0, b0, 0, bufB, 256);
    bn_finalize_kernel<<<1, 256>>>(g0, be0, 256);

    // layer 1: in bufB (BN0+ReLU fused on load), out bufA (256 ch)
    gemm_bf16x3_kernel<<<dim3(Rr / 64, 2), 256, SMEM_GEMM_BYTES>>>(bufB, w1, b1, 1, bufA, 256);
    bn_finalize_kernel<<<1, 256>>>(g1, be1, 256);

    // layer 2: in bufA (BN1+ReLU fused on load), out bufB (128 ch)
    gemm_bf16x3_kernel<<<dim3(Rr / 64, 1), 256, SMEM_GEMM_BYTES>>>(bufA, w2, b2, 1, bufB, 128);
    bn_finalize_kernel<<<1, 256>>>(g2, be2, 128);

    // output: [q | BN2+ReLU(h) transposed to [B,128,N]]
    if (qoff)
        cudaMemcpyAsync(out, q, (size_t)Qfloats * sizeof(float),
                        cudaMemcpyDeviceToDevice);
    output_kernel<<<dim3(Np / 32, 4, Bb), dim3(32, 8)>>>(bufB, out + qoff);
}

// round 10
// speedup vs baseline: 1.2917x; 1.0172x over previous
#include <cuda_runtime.h>
#include <cstddef>
#include <cstdint>

// Problem constants
#define Bb 8
#define Np 8192
#define Mp 1024
#define Cc 256
#define Rr (Bb*Np)       // 65536 rows
#define BN_EPS 1e-5f

// Scratch (static __device__ — no allocations allowed)
__device__ float g_bufA[(size_t)Rr*Cc];     // 64 MB
__device__ float g_bufB[(size_t)Rr*Cc];     // 64 MB
__device__ float g_xT[(size_t)Bb*Mp*Cc];    // 8 MB
__device__ float g_sum[Cc];
__device__ float g_sumsq[Cc];
__device__ float g_scale[Cc];
__device__ float g_shift[Cc];

// ---------------------------------------------------------------------------
__global__ void zero_stats_kernel() {
    int t = threadIdx.x;
    g_sum[t] = 0.f; g_sumsq[t] = 0.f;
}

// ---------------------------------------------------------------------------
// transpose x[b][c][m] -> xT[b][m][c]
__global__ void transpose_x_kernel(const float* __restrict__ x, float* __restrict__ xT) {
    __shared__ float t[32][33];
    int b = blockIdx.z;
    int m0 = blockIdx.x * 32, c0 = blockIdx.y * 32;
    int tx = threadIdx.x, ty = threadIdx.y; // 32 x 8
    const float* xb = x + (size_t)b * Cc * Mp;
    #pragma unroll
    for (int k = 0; k < 32; k += 8)
        t[ty + k][tx] = xb[(size_t)(c0 + ty + k) * Mp + m0 + tx];
    __syncthreads();
    float* ob = xT + (size_t)b * Mp * Cc;
    #pragma unroll
    for (int k = 0; k < 32; k += 8)
        ob[(size_t)(m0 + ty + k) * Cc + c0 + tx] = t[tx][ty + k];
}

// ---------------------------------------------------------------------------
// 3-NN + inverse-distance-weighted interpolation. Writes h0 in [b][n][c].
// Even/odd 2-chain top-3 scan for ILP; float4-vectorized gather.
__global__ void knn_interp_kernel(const float* __restrict__ p,
                                  const float* __restrict__ q,
                                  const float* __restrict__ xT,
                                  float* __restrict__ h0) {
    __shared__ float sqx[Mp], sqy[Mp], sqz[Mp], sqq[Mp];
    __shared__ float sw[128][3];
    __shared__ int   si[128][3];
    const int b = blockIdx.x;
    const int n0 = blockIdx.y * 128;
    const int tid = threadIdx.x;

    for (int m = tid; m < Mp; m += 128) {
        float qx = q[((size_t)b * Mp + m) * 3 + 0];
        float qy = q[((size_t)b * Mp + m) * 3 + 1];
        float qz = q[((size_t)b * Mp + m) * 3 + 2];
        sqx[m] = qx; sqy[m] = qy; sqz[m] = qz;
        sqq[m] = qx * qx + qy * qy + qz * qz;
    }
    __syncthreads();

    const int n = n0 + tid;
    float px = p[((size_t)b * Np + n) * 3 + 0];
    float py = p[((size_t)b * Np + n) * 3 + 1];
    float pz = p[((size_t)b * Np + n) * 3 + 2];
    float pp = px * px + py * py + pz * pz;

    float e0 = 3.4e38f, e1 = 3.4e38f, e2 = 3.4e38f;
    int   ei0 = 0, ei1 = 0, ei2 = 0;
    float o0 = 3.4e38f, o1 = 3.4e38f, o2 = 3.4e38f;
    int   oi0 = 0, oi1 = 0, oi2 = 0;
    #pragma unroll 2
    for (int m = 0; m < Mp; m += 2) {
        float dotE = px * sqx[m] + py * sqy[m] + pz * sqz[m];
        float dE = pp + sqq[m] - 2.f * dotE;
        float dotO = px * sqx[m+1] + py * sqy[m+1] + pz * sqz[m+1];
        float dO = pp + sqq[m+1] - 2.f * dotO;
        if (dE < e2) {
            if (dE < e1) {
                e2 = e1; ei2 = ei1;
                if (dE < e0) { e1 = e0; ei1 = ei0; e0 = dE; ei0 = m; }
                else         { e1 = dE; ei1 = m; }
            } else { e2 = dE; ei2 = m; }
        }
        if (dO < o2) {
            if (dO < o1) {
                o2 = o1; oi2 = oi1;
                if (dO < o0) { o1 = o0; oi1 = oi0; o0 = dO; oi0 = m+1; }
                else         { o1 = dO; oi1 = m+1; }
            } else { o2 = dO; oi2 = m+1; }
        }
    }
    #pragma unroll
    for (int c = 0; c < 3; c++) {
        float d = (c == 0) ? o0 : (c == 1) ? o1 : o2;
        int   i = (c == 0) ? oi0 : (c == 1) ? oi1 : oi2;
        if (d < e2) {
            if (d < e1) {
                e2 = e1; ei2 = ei1;
                if (d < e0) { e1 = e0; ei1 = ei0; e0 = d; ei0 = i; }
                else        { e1 = d; ei1 = i; }
            } else { e2 = d; ei2 = i; }
        }
    }
    float a0 = 1.f / fmaxf(e0, 1e-10f);
    float a1 = 1.f / fmaxf(e1, 1e-10f);
    float a2 = 1.f / fmaxf(e2, 1e-10f);
    float inv = 1.f / (a0 + a1 + a2);
    sw[tid][0] = a0 * inv; sw[tid][1] = a1 * inv; sw[tid][2] = a2 * inv;
    si[tid][0] = ei0; si[tid][1] = ei1; si[tid][2] = ei2;
    __syncthreads();

    const int lane = tid & 31, warp = tid >> 5;
    const float* xb = xT + (size_t)b * Mp * Cc;
    for (int nl = warp * 32; nl < warp * 32 + 32; nl++) {
        float w0 = sw[nl][0], w1 = sw[nl][1], w2 = sw[nl][2];
        const float4* r0 = (const float4*)(xb + (size_t)si[nl][0] * Cc);
        const float4* r1 = (const float4*)(xb + (size_t)si[nl][1] * Cc);
        const float4* r2 = (const float4*)(xb + (size_t)si[nl][2] * Cc);
        float4* o4 = (float4*)(h0 + ((size_t)b * Np + n0 + nl) * Cc);
        #pragma unroll
        for (int c = lane; c < Cc / 4; c += 32) {
            float4 a = r0[c], bq = r1[c], cq = r2[c];
            float4 v;
            v.x = w0 * a.x + w1 * bq.x + w2 * cq.x;
            v.y = w0 * a.y + w1 * bq.y + w2 * cq.y;
            v.z = w0 * a.z + w1 * bq.z + w2 * cq.z;
            v.w = w0 * a.w + w1 * bq.w + w2 * cq.w;
            o4[c] = v;
        }
    }
}

// ---------------------------------------------------------------------------
// bf16x3 emulated-fp32 GEMM via legacy mma.sync (sm_80 PTX path)
// ---------------------------------------------------------------------------
__device__ __forceinline__ uint32_t prmt_hi(uint32_t a, uint32_t b) {
    uint32_t r; asm("prmt.b32 %0, %1, %2, 0x7632;" : "=r"(r) : "r"(a), "r"(b));
    return r;   // {lo16 = a.hi16, hi16 = b.hi16}
}
__device__ __forceinline__ uint32_t pack_bf16_rn(float lo0, float lo1) {
    uint32_t r; asm("cvt.rn.bf16x2.f32 %0, %1, %2;" : "=r"(r) : "f"(lo1), "f"(lo0));
    return r;   // low half = lo0
}
__device__ __forceinline__ float trunc_hi_f(float f) {
    return __uint_as_float(__float_as_uint(f) & 0xFFFF0000u);
}

#define MMA_BF16(c, a, b0v, b1v) \
    asm volatile("mma.sync.aligned.m16n8k16.row.col.f32.bf16.bf16.f32 " \
        "{%0,%1,%2,%3},{%4,%5,%6,%7},{%8,%9},{%0,%1,%2,%3};" \
        : "+f"((c)[0]), "+f"((c)[1]), "+f"((c)[2]), "+f"((c)[3]) \
        : "r"((a).x), "r"((a).y), "r"((a).z), "r"((a).w), "r"(b0v), "r"(b1v))

#define LDMATRIX_X4(r, addr) \
    asm volatile("ldmatrix.sync.aligned.m8n8.x4.shared.b16 {%0,%1,%2,%3}, [%4];" \
        : "=r"((r).x), "=r"((r).y), "=r"((r).z), "=r"((r).w) : "r"(addr))

// smem tiles: bf16, row-major, rows x 32 k = 64 B/row, XOR-granule swizzle.
// addr(row, kg) = row*64 + (kg ^ ((row>>1)&3))*16        (kg = 16B granule 0..3)
// Stage layout: A_hi(4K) A_lo(4K) B_hi(8K) B_lo(8K) = 24 KB; 4 stages = 96 KB.
#define A_TILE   4096                 // 64 rows x 64 B
#define B_TILE   8192                 // 128 rows x 64 B
#define STAGE_B  (2 * A_TILE + 2 * B_TILE)   // 24576
#define SMEM_GEMM_BYTES (4 * STAGE_B)        // 98304

// out[r][o] = sum_c act(A[r][c]) * W[o][c] + bias[o], K=256, CTA tile 64x128.
// 256 threads, 8 warps (2M x 4N), 2 CTAs/SM. 4-stage ring, one barrier per
// TWO K-blocks (stores kb+2/kb+3 while consuming kb/kb+1; LDG issued one MMA
// block ahead of its STS). BN stats fused into epilogue.
__global__ void __launch_bounds__(256, 2)
gemm_bf16x3_kernel(const float* __restrict__ A, const float* __restrict__ W,
                   const float* __restrict__ bias, int useAct,
                   float* __restrict__ out, int O) {
    extern __shared__ char smc[];
    const int tid = threadIdx.x;
    const int lane = tid & 31, wid = tid >> 5;
    const int wm = wid >> 2, wn = wid & 3;           // 2M x 4N
    const size_t rowBase = (size_t)blockIdx.x * 64;
    const int colBase = blockIdx.y * 128;

    const uint32_t smb = (uint32_t)__cvta_generic_to_shared(smc);

    // producer mapping: prow = tid>>2 (0..63), pkg = tid&3 (8 k each)
    const int prow = tid >> 2;
    const int pkg = tid & 3;
    const uint32_t swz = (uint32_t)((pkg ^ ((prow >> 1) & 3)) << 4);
    const uint32_t aSlot  = (uint32_t)(prow * 64) + swz;
    const uint32_t bSlot0 = (uint32_t)(prow * 64) + swz;
    const uint32_t bSlot1 = (uint32_t)((prow + 64) * 64) +
                            (uint32_t)((pkg ^ (((prow + 64) >> 1) & 3)) << 4);
    const float* aG = A + (rowBase + prow) * 256 + pkg * 8;
    const float* wG0 = W + (size_t)(colBase + prow) * 256 + pkg * 8;
    const float* wG1 = W + (size_t)(colBase + prow + 64) * 256 + pkg * 8;

    float acc[2][4][4];
    #pragma unroll
    for (int i = 0; i < 2; i++)
        #pragma unroll
        for (int j = 0; j < 4; j++)
            #pragma unroll
            for (int r = 0; r < 4; r++) acc[i][j][r] = 0.f;

    float4 va0, va1, vb0, vb1, vb2, vb3;
    auto loadG = [&](int kb) {
        va0 = *(const float4*)(aG + kb * 32);
        va1 = *(const float4*)(aG + kb * 32 + 4);
        vb0 = *(const float4*)(wG0 + kb * 32);
        vb1 = *(const float4*)(wG0 + kb * 32 + 4);
        vb2 = *(const float4*)(wG1 + kb * 32);
        vb3 = *(const float4*)(wG1 + kb * 32 + 4);
    };
    auto cvt8 = [&](const float* a, uint4& hi, uint4& lo) {
        hi.x = prmt_hi(__float_as_uint(a[0]), __float_as_uint(a[1]));
        hi.y = prmt_hi(__float_as_uint(a[2]), __float_as_uint(a[3]));
        hi.z = prmt_hi(__float_as_uint(a[4]), __float_as_uint(a[5]));
        hi.w = prmt_hi(__float_as_uint(a[6]), __float_as_uint(a[7]));
        lo.x = pack_bf16_rn(a[0] - trunc_hi_f(a[0]), a[1] - trunc_hi_f(a[1]));
        lo.y = pack_bf16_rn(a[2] - trunc_hi_f(a[2]), a[3] - trunc_hi_f(a[3]));
        lo.z = pack_bf16_rn(a[4] - trunc_hi_f(a[4]), a[5] - trunc_hi_f(a[5]));
        lo.w = pack_bf16_rn(a[6] - trunc_hi_f(a[6]), a[7] - trunc_hi_f(a[7]));
    };
    auto storeS = [&](int s, int kb) {
        const uint32_t stg = smb + s * STAGE_B;
        float a[8] = {va0.x, va0.y, va0.z, va0.w, va1.x, va1.y, va1.z, va1.w};
        if (useAct) {
            int c = kb * 32 + pkg * 8;
            #pragma unroll
            for (int j = 0; j < 8; j++)
                a[j] = fmaxf(fmaf(a[j], g_scale[c + j], g_shift[c + j]), 0.f);
        }
        uint4 hi, lo;
        cvt8(a, hi, lo);
        asm volatile("st.shared.v4.b32 [%0], {%1,%2,%3,%4};"
                     :: "r"(stg + aSlot), "r"(hi.x), "r"(hi.y), "r"(hi.z), "r"(hi.w));
        asm volatile("st.shared.v4.b32 [%0], {%1,%2,%3,%4};"
                     :: "r"(stg + A_TILE + aSlot), "r"(lo.x), "r"(lo.y), "r"(lo.z), "r"(lo.w));

        float b0a[8] = {vb0.x, vb0.y, vb0.z, vb0.w, vb1.x, vb1.y, vb1.z, vb1.w};
        cvt8(b0a, hi, lo);
        asm volatile("st.shared.v4.b32 [%0], {%1,%2,%3,%4};"
                     :: "r"(stg + 2 * A_TILE + bSlot0), "r"(hi.x), "r"(hi.y), "r"(hi.z), "r"(hi.w));
        asm volatile("st.shared.v4.b32 [%0], {%1,%2,%3,%4};"
                     :: "r"(stg + 2 * A_TILE + B_TILE + bSlot0), "r"(lo.x), "r"(lo.y), "r"(lo.z), "r"(lo.w));

        float b1a[8] = {vb2.x, vb2.y, vb2.z, vb2.w, vb3.x, vb3.y, vb3.z, vb3.w};
        cvt8(b1a, hi, lo);
        asm volatile("st.shared.v4.b32 [%0], {%1,%2,%3,%4};"
                     :: "r"(stg + 2 * A_TILE + bSlot1), "r"(hi.x), "r"(hi.y), "r"(hi.z), "r"(hi.w));
        asm volatile("st.shared.v4.b32 [%0], {%1,%2,%3,%4};"
                     :: "r"(stg + 2 * A_TILE + B_TILE + bSlot1), "r"(lo.x), "r"(lo.y), "r"(lo.z), "r"(lo.w));
    };

    // consumer per-lane ldmatrix offsets (within stage), precomputed
    const int aRow0 = wm * 32 + ((lane >> 3) & 1) * 8 + (lane & 7);
    const int aKh = (lane >> 4) & 1;
    const int bRow0 = wn * 32 + ((lane >> 4) & 1) * 8 + (lane & 7);
    const int bKh = (lane >> 3) & 1;
    uint32_t aOff[2][2], bOff[2][2];   // [mt|p][ks]
    #pragma unroll
    for (int mt = 0; mt < 2; mt++) {
        int row = aRow0 + mt * 16;
        #pragma unroll
        for (int ks = 0; ks < 2; ks++)
            aOff[mt][ks] = (uint32_t)(row * 64 + ((((ks << 1) + aKh) ^ ((row >> 1) & 3)) << 4));
    }
    #pragma unroll
    for (int p = 0; p < 2; p++) {
        int row = bRow0 + p * 16;
        #pragma unroll
        for (int ks = 0; ks < 2; ks++)
            bOff[p][ks] = (uint32_t)(2 * A_TILE + row * 64 + ((((ks << 1) + bKh) ^ ((row >> 1) & 3)) << 4));
    }

    // consumer: MMAs for one K-block from stage s
    auto consume = [&](int s) {
        const uint32_t stg = smb + s * STAGE_B;
        uint4 ah[2], al[2], bh[2][2], bl[2][2];
        #pragma unroll
        for (int mt = 0; mt < 2; mt++) {
            LDMATRIX_X4(ah[mt], stg + aOff[mt][0]);
            LDMATRIX_X4(al[mt], stg + aOff[mt][0] + A_TILE);
        }
        #pragma unroll
        for (int p = 0; p < 2; p++) {
            LDMATRIX_X4(bh[0][p], stg + bOff[p][0]);
            LDMATRIX_X4(bl[0][p], stg + bOff[p][0] + B_TILE);
        }
        #pragma unroll
        for (int p = 0; p < 2; p++) {
            LDMATRIX_X4(bh[1][p], stg + bOff[p][1]);
            LDMATRIX_X4(bl[1][p], stg + bOff[p][1] + B_TILE);
        }
        #pragma unroll
        for (int mt = 0; mt < 2; mt++) {
            #pragma unroll
            for (int p = 0; p < 2; p++) {
                MMA_BF16(acc[mt][2*p],   ah[mt], bh[0][p].x, bh[0][p].y);
                MMA_BF16(acc[mt][2*p],   ah[mt], bl[0][p].x, bl[0][p].y);
                MMA_BF16(acc[mt][2*p],   al[mt], bh[0][p].x, bh[0][p].y);
                MMA_BF16(acc[mt][2*p+1], ah[mt], bh[0][p].z, bh[0][p].w);
                MMA_BF16(acc[mt][2*p+1], ah[mt], bl[0][p].z, bl[0][p].w);
                MMA_BF16(acc[mt][2*p+1], al[mt], bh[0][p].z, bh[0][p].w);
            }
        }
        #pragma unroll
        for (int mt = 0; mt < 2; mt++) {
            LDMATRIX_X4(ah[mt], stg + aOff[mt][1]);
            LDMATRIX_X4(al[mt], stg + aOff[mt][1] + A_TILE);
        }
        #pragma unroll
        for (int mt = 0; mt < 2; mt++) {
            #pragma unroll
            for (int p = 0; p < 2; p++) {
                MMA_BF16(acc[mt][2*p],   ah[mt], bh[1][p].x, bh[1][p].y);
                MMA_BF16(acc[mt][2*p],   ah[mt], bl[1][p].x, bl[1][p].y);
                MMA_BF16(acc[mt][2*p],   al[mt], bh[1][p].x, bh[1][p].y);
                MMA_BF16(acc[mt][2*p+1], ah[mt], bh[1][p].z, bh[1][p].w);
                MMA_BF16(acc[mt][2*p+1], ah[mt], bl[1][p].z, bl[1][p].w);
                MMA_BF16(acc[mt][2*p+1], al[mt], bh[1][p].z, bh[1][p].w);
            }
        }
    };

    // prologue: stages 0,1
    loadG(0); storeS(0, 0);
    loadG(1); storeS(1, 1);
    __syncthreads();

    // mainloop: one barrier per 2 K-blocks
    #pragma unroll 1
    for (int kbp = 0; kbp < 8; kbp += 2) {
        if (kbp + 2 < 8) loadG(kbp + 2);
        consume(kbp & 3);
        if (kbp + 2 < 8) storeS((kbp + 2) & 3, kbp + 2);
        if (kbp + 3 < 8) loadG(kbp + 3);
        consume((kbp + 1) & 3);
        if (kbp + 3 < 8) storeS((kbp + 3) & 3, kbp + 3);
        if (kbp + 2 < 8) __syncthreads();
    }

    // epilogue: +bias, store, fused per-channel stats
    float sp[8], ssp[8];
    #pragma unroll
    for (int c = 0; c < 8; c++) { sp[c] = 0.f; ssp[c] = 0.f; }

    const int gId = lane >> 2, l4 = lane & 3;
    #pragma unroll
    for (int mt = 0; mt < 2; mt++) {
        size_t row0 = rowBase + wm * 32 + mt * 16 + gId;
        #pragma unroll
        for (int nt = 0; nt < 4; nt++) {
            int col0 = colBase + wn * 32 + nt * 8 + 2 * l4;
            float b0 = bias[col0], b1 = bias[col0 + 1];
            float v00 = acc[mt][nt][0] + b0, v01 = acc[mt][nt][1] + b1;
            float v10 = acc[mt][nt][2] + b0, v11 = acc[mt][nt][3] + b1;
            *(float2*)(out + row0 * O + col0)        = make_float2(v00, v01);
            *(float2*)(out + (row0 + 8) * O + col0)  = make_float2(v10, v11);
            sp[nt * 2 + 0]  += v00 + v10;
            sp[nt * 2 + 1]  += v01 + v11;
            ssp[nt * 2 + 0] += v00 * v00 + v10 * v10;
            ssp[nt * 2 + 1] += v01 * v01 + v11 * v11;
        }
    }
    #pragma unroll
    for (int c = 0; c < 8; c++) {
        #pragma unroll
        for (int mask = 4; mask <= 16; mask <<= 1) {
            sp[c]  += __shfl_xor_sync(0xffffffffu, sp[c],  mask);
            ssp[c] += __shfl_xor_sync(0xffffffffu, ssp[c], mask);
        }
    }
    if (lane < 4) {
        #pragma unroll
        for (int nt = 0; nt < 4; nt++) {
            #pragma unroll
            for (int h = 0; h < 2; h++) {
                int col = colBase + wn * 32 + nt * 8 + 2 * lane + h;
                atomicAdd(&g_sum[col],   sp[nt * 2 + h]);
                atomicAdd(&g_sumsq[col], ssp[nt * 2 + h]);
            }
        }
    }
}

// ---------------------------------------------------------------------------
// fold BN into per-channel affine: scale = gamma*rsqrt(var+eps), shift = beta - mu*scale
__global__ void bn_finalize_kernel(const float* __restrict__ g,
                                   const float* __restrict__ beta, int O) {
    int t = threadIdx.x; // 256 threads always
    if (t < O) {
        const float cnt = (float)Rr;
        float mu  = g_sum[t] / cnt;
        float var = fmaxf(g_sumsq[t] / cnt - mu * mu, 0.f);
        float sc  = rsqrtf(var + BN_EPS) * g[t];
        g_scale[t] = sc;
        g_shift[t] = beta[t] - mu * sc;
    }
    g_sum[t] = 0.f; g_sumsq[t] = 0.f;
}

// ---------------------------------------------------------------------------
// final BN+ReLU + transpose [b][n][o] -> [b][o][n] into d_out (O = 128)
__global__ void output_kernel(const float* __restrict__ in, float* __restrict__ out) {
    __shared__ float t[32][33];
    const int b = blockIdx.z;
    const int n0 = blockIdx.x * 32, o0 = blockIdx.y * 32;
    const int tx = threadIdx.x, ty = threadIdx.y; // 32 x 8
    #pragma unroll
    for (int k = 0; k < 32; k += 8) {
        int o = o0 + tx;
        float v = in[((size_t)b * Np + n0 + ty + k) * 128 + o];
        t[ty + k][tx] = fmaxf(fmaf(v, g_scale[o], g_shift[o]), 0.f);
    }
    __syncthreads();
    #pragma unroll
    for (int k = 0; k < 32; k += 8)
        out[((size_t)b * 128 + o0 + ty + k) * Np + n0 + tx] = t[tx][ty + k];
}

// ---------------------------------------------------------------------------
extern "C" void kernel_launch(void* const* d_in, const int* in_sizes, int n_in,
                              void* d_out, int out_size) {
    const float* p   = (const float*)d_in[0];
    const float* q   = (const float*)d_in[1];
    const float* x   = (const float*)d_in[2];
    const float* w0  = (const float*)d_in[3];
    const float* b0  = (const float*)d_in[4];
    const float* g0  = (const float*)d_in[5];
    const float* be0 = (const float*)d_in[6];
    const float* w1  = (const float*)d_in[7];
    const float* b1  = (const float*)d_in[8];
    const float* g1  = (const float*)d_in[9];
    const float* be1 = (const float*)d_in[10];
    const float* w2  = (const float*)d_in[11];
    const float* b2  = (const float*)d_in[12];
    const float* g2  = (const float*)d_in[13];
    const float* be2 = (const float*)d_in[14];
    float* out = (float*)d_out;

    float *bufA, *bufB, *xT;
    cudaGetSymbolAddress((void**)&bufA, g_bufA);
    cudaGetSymbolAddress((void**)&bufB, g_bufB);
    cudaGetSymbolAddress((void**)&xT,  g_xT);

    const int Qfloats = Bb * Mp * 3;                    // 24576
    const int Hfloats = Bb * 128 * Np;                  // 8388608
    const int qoff = (out_size >= Qfloats + Hfloats) ? Qfloats : 0;

    cudaFuncSetAttribute(gemm_bf16x3_kernel,
                         cudaFuncAttributeMaxDynamicSharedMemorySize, SMEM_GEMM_BYTES);

    zero_stats_kernel<<<1, 256>>>();
    transpose_x_kernel<<<dim3(Mp / 32, Cc / 32, Bb), dim3(32, 8)>>>(x, xT);
    knn_interp_kernel<<<dim3(Bb, Np / 128), 128>>>(p, q, xT, bufA);

    // layer 0: in bufA (raw), out bufB (256 ch) — stats fused
    gemm_bf16x3_kernel<<<dim3(Rr / 64, 2), 256, SMEM_GEMM_BYTES>>>(bufA, w0, b0, 0, bufB, 256);
    bn_finalize_kernel<<<1, 256>>>(g0, be0, 256);

    // layer 1: in bufB (BN0+ReLU fused on load), out bufA (256 ch)
    gemm_bf16x3_kernel<<<dim3(Rr / 64, 2), 256, SMEM_GEMM_BYTES>>>(bufB, w1, b1, 1, bufA, 256);
    bn_finalize_kernel<<<1, 256>>>(g1, be1, 256);

    // layer 2: in bufA (BN1+ReLU fused on load), out bufB (128 ch)
    gemm_bf16x3_kernel<<<dim3(Rr / 64, 1), 256, SMEM_GEMM_BYTES>>>(bufA, w2, b2, 1, bufB, 128);
    bn_finalize_kernel<<<1, 256>>>(g2, be2, 128);

    // output: [q | BN2+ReLU(h) transposed to [B,128,N]]
    if (qoff)
        cudaMemcpyAsync(out, q, (size_t)Qfloats * sizeof(float),
                        cudaMemcpyDeviceToDevice);
    output_kernel<<<dim3(Np / 32, 4, Bb), dim3(32, 8)>>>(bufB, out + qoff);
}

// round 12
// speedup vs baseline: 1.3114x; 1.0152x over previous
#include <cuda_runtime.h>
#include <cstddef>
#include <cstdint>

// Problem constants
#define Bb 8
#define Np 8192
#define Mp 1024
#define Cc 256
#define Rr (Bb*Np)       // 65536 rows
#define BN_EPS 1e-5f

// Scratch (static __device__ — no allocations allowed)
__device__ float g_bufA[(size_t)Rr*Cc];     // 64 MB
__device__ float g_bufB[(size_t)Rr*Cc];     // 64 MB
__device__ float g_xT[(size_t)Bb*Mp*Cc];    // 8 MB
__device__ float g_sum0[Cc],  g_sumsq0[Cc];
__device__ float g_sum1[Cc],  g_sumsq1[Cc];
__device__ float g_sum2[Cc],  g_sumsq2[Cc];

// ---------------------------------------------------------------------------
__global__ void zero_stats_kernel() {
    int t = threadIdx.x;
    g_sum0[t] = 0.f; g_sumsq0[t] = 0.f;
    g_sum1[t] = 0.f; g_sumsq1[t] = 0.f;
    g_sum2[t] = 0.f; g_sumsq2[t] = 0.f;
}

// ---------------------------------------------------------------------------
// transpose x[b][c][m] -> xT[b][m][c]
__global__ void transpose_x_kernel(const float* __restrict__ x, float* __restrict__ xT) {
    __shared__ float t[32][33];
    int b = blockIdx.z;
    int m0 = blockIdx.x * 32, c0 = blockIdx.y * 32;
    int tx = threadIdx.x, ty = threadIdx.y; // 32 x 8
    const float* xb = x + (size_t)b * Cc * Mp;
    #pragma unroll
    for (int k = 0; k < 32; k += 8)
        t[ty + k][tx] = xb[(size_t)(c0 + ty + k) * Mp + m0 + tx];
    __syncthreads();
    float* ob = xT + (size_t)b * Mp * Cc;
    #pragma unroll
    for (int k = 0; k < 32; k += 8)
        ob[(size_t)(m0 + ty + k) * Cc + c0 + tx] = t[tx][ty + k];
}

// ---------------------------------------------------------------------------
// 3-NN + inverse-distance-weighted interpolation. Writes h0 in [b][n][c].
// 256 threads: two threads split each point's scan (512 each, even/odd ILP
// chains), merge in smem; gather with 8 warps.
__global__ void knn_interp_kernel(const float* __restrict__ p,
                                  const float* __restrict__ q,
                                  const float* __restrict__ xT,
                                  float* __restrict__ h0) {
    __shared__ float sqx[Mp], sqy[Mp], sqz[Mp], sqq[Mp];
    __shared__ float sd[256][3];
    __shared__ int   sdi[256][3];
    __shared__ float sw[128][3];
    __shared__ int   si[128][3];
    const int b = blockIdx.x;
    const int n0 = blockIdx.y * 128;
    const int tid = threadIdx.x;       // 256

    for (int m = tid; m < Mp; m += 256) {
        float qx = q[((size_t)b * Mp + m) * 3 + 0];
        float qy = q[((size_t)b * Mp + m) * 3 + 1];
        float qz = q[((size_t)b * Mp + m) * 3 + 2];
        sqx[m] = qx; sqy[m] = qy; sqz[m] = qz;
        sqq[m] = qx * qx + qy * qy + qz * qz;
    }
    __syncthreads();

    const int pt = tid & 127;          // point index
    const int half = tid >> 7;         // scan half
    const int n = n0 + pt;
    float px = p[((size_t)b * Np + n) * 3 + 0];
    float py = p[((size_t)b * Np + n) * 3 + 1];
    float pz = p[((size_t)b * Np + n) * 3 + 2];
    float pp = px * px + py * py + pz * pz;

    float e0 = 3.4e38f, e1 = 3.4e38f, e2 = 3.4e38f;
    int   ei0 = 0, ei1 = 0, ei2 = 0;
    float o0 = 3.4e38f, o1 = 3.4e38f, o2 = 3.4e38f;
    int   oi0 = 0, oi1 = 0, oi2 = 0;
    const int mBase = half * 512;
    #pragma unroll 2
    for (int m = mBase; m < mBase + 512; m += 2) {
        float dotE = px * sqx[m] + py * sqy[m] + pz * sqz[m];
        float dE = pp + sqq[m] - 2.f * dotE;
        float dotO = px * sqx[m+1] + py * sqy[m+1] + pz * sqz[m+1];
        float dO = pp + sqq[m+1] - 2.f * dotO;
        if (dE < e2) {
            if (dE < e1) {
                e2 = e1; ei2 = ei1;
                if (dE < e0) { e1 = e0; ei1 = ei0; e0 = dE; ei0 = m; }
                else         { e1 = dE; ei1 = m; }
            } else { e2 = dE; ei2 = m; }
        }
        if (dO < o2) {
            if (dO < o1) {
                o2 = o1; oi2 = oi1;
                if (dO < o0) { o1 = o0; oi1 = oi0; o0 = dO; oi0 = m+1; }
                else         { o1 = dO; oi1 = m+1; }
            } else { o2 = dO; oi2 = m+1; }
        }
    }
    // merge odd chain into even chain (within this half)
    #pragma unroll
    for (int c = 0; c < 3; c++) {
        float d = (c == 0) ? o0 : (c == 1) ? o1 : o2;
        int   i = (c == 0) ? oi0 : (c == 1) ? oi1 : oi2;
        if (d < e2) {
            if (d < e1) {
                e2 = e1; ei2 = ei1;
                if (d < e0) { e1 = e0; ei1 = ei0; e0 = d; ei0 = i; }
                else        { e1 = d; ei1 = i; }
            } else { e2 = d; ei2 = i; }
        }
    }
    sd[tid][0] = e0;  sd[tid][1] = e1;  sd[tid][2] = e2;
    sdi[tid][0] = ei0; sdi[tid][1] = ei1; sdi[tid][2] = ei2;
    __syncthreads();

    if (tid < 128) {
        // merge the two halves' top-3
        float m0 = sd[tid][0], m1 = sd[tid][1], m2 = sd[tid][2];
        int   j0 = sdi[tid][0], j1 = sdi[tid][1], j2 = sdi[tid][2];
        #pragma unroll
        for (int c = 0; c < 3; c++) {
            float d = sd[tid + 128][c];
            int   i = sdi[tid + 128][c];
            if (d < m2) {
                if (d < m1) {
                    m2 = m1; j2 = j1;
                    if (d < m0) { m1 = m0; j1 = j0; m0 = d; j0 = i; }
                    else        { m1 = d; j1 = i; }
                } else { m2 = d; j2 = i; }
            }
        }
        float a0 = 1.f / fmaxf(m0, 1e-10f);
        float a1 = 1.f / fmaxf(m1, 1e-10f);
        float a2 = 1.f / fmaxf(m2, 1e-10f);
        float inv = 1.f / (a0 + a1 + a2);
        sw[tid][0] = a0 * inv; sw[tid][1] = a1 * inv; sw[tid][2] = a2 * inv;
        si[tid][0] = j0; si[tid][1] = j1; si[tid][2] = j2;
    }
    __syncthreads();

    const int lane = tid & 31, warp = tid >> 5;   // 8 warps x 16 points
    const float* xb = xT + (size_t)b * Mp * Cc;
    for (int nl = warp * 16; nl < warp * 16 + 16; nl++) {
        float w0 = sw[nl][0], w1 = sw[nl][1], w2 = sw[nl][2];
        const float4* r0 = (const float4*)(xb + (size_t)si[nl][0] * Cc);
        const float4* r1 = (const float4*)(xb + (size_t)si[nl][1] * Cc);
        const float4* r2 = (const float4*)(xb + (size_t)si[nl][2] * Cc);
        float4* o4 = (float4*)(h0 + ((size_t)b * Np + n0 + nl) * Cc);
        #pragma unroll
        for (int c = lane; c < Cc / 4; c += 32) {
            float4 a = r0[c], bq = r1[c], cq = r2[c];
            float4 v;
            v.x = w0 * a.x + w1 * bq.x + w2 * cq.x;
            v.y = w0 * a.y + w1 * bq.y + w2 * cq.y;
            v.z = w0 * a.z + w1 * bq.z + w2 * cq.z;
            v.w = w0 * a.w + w1 * bq.w + w2 * cq.w;
            o4[c] = v;
        }
    }
}

// ---------------------------------------------------------------------------
// bf16x3 emulated-fp32 GEMM via legacy mma.sync (sm_80 PTX path)
// ---------------------------------------------------------------------------
__device__ __forceinline__ uint32_t prmt_hi(uint32_t a, uint32_t b) {
    uint32_t r; asm("prmt.b32 %0, %1, %2, 0x7632;" : "=r"(r) : "r"(a), "r"(b));
    return r;   // {lo16 = a.hi16, hi16 = b.hi16}
}
__device__ __forceinline__ uint32_t pack_bf16_rn(float lo0, float lo1) {
    uint32_t r; asm("cvt.rn.bf16x2.f32 %0, %1, %2;" : "=r"(r) : "f"(lo1), "f"(lo0));
    return r;   // low half = lo0
}
__device__ __forceinline__ float trunc_hi_f(float f) {
    return __uint_as_float(__float_as_uint(f) & 0xFFFF0000u);
}

#define MMA_BF16(c, a, b0v, b1v) \
    asm volatile("mma.sync.aligned.m16n8k16.row.col.f32.bf16.bf16.f32 " \
        "{%0,%1,%2,%3},{%4,%5,%6,%7},{%8,%9},{%0,%1,%2,%3};" \
        : "+f"((c)[0]), "+f"((c)[1]), "+f"((c)[2]), "+f"((c)[3]) \
        : "r"((a).x), "r"((a).y), "r"((a).z), "r"((a).w), "r"(b0v), "r"(b1v))

#define LDMATRIX_X4(r, addr) \
    asm volatile("ldmatrix.sync.aligned.m8n8.x4.shared.b16 {%0,%1,%2,%3}, [%4];" \
        : "=r"((r).x), "=r"((r).y), "=r"((r).z), "=r"((r).w) : "r"(addr))

// smem tiles: bf16, row-major, rows x 32 k = 64 B/row, XOR-granule swizzle.
// Stage layout: A_hi(4K) A_lo(4K) B_hi(8K) B_lo(8K) = 24 KB; 4 stages = 96 KB.
#define A_TILE   4096
#define B_TILE   8192
#define STAGE_B  (2 * A_TILE + 2 * B_TILE)   // 24576
#define SMEM_GEMM_BYTES (4 * STAGE_B)        // 98304

// out[r][o] = sum_c act(A[r][c]) * W[o][c] + bias[o], K=256, CTA tile 64x128.
// 256 threads, 8 warps (2M x 4N), 2 CTAs/SM, 4-stage ring, barrier per 2 kb.
// BN(prev layer) folded per-CTA from raw sums; BN stats fused into epilogue.
__global__ void __launch_bounds__(256, 2)
gemm_bf16x3_kernel(const float* __restrict__ A, const float* __restrict__ W,
                   const float* __restrict__ bias,
                   const float* __restrict__ prevSum, const float* __restrict__ prevSumsq,
                   const float* __restrict__ prevG, const float* __restrict__ prevBeta,
                   int useAct, float* __restrict__ out, int O,
                   float* __restrict__ sumArr, float* __restrict__ sumsqArr) {
    extern __shared__ char smc[];
    __shared__ float s_scale[Cc], s_shift[Cc];
    const int tid = threadIdx.x;
    const int lane = tid & 31, wid = tid >> 5;
    const int wm = wid >> 2, wn = wid & 3;           // 2M x 4N
    const size_t rowBase = (size_t)blockIdx.x * 64;
    const int colBase = blockIdx.y * 128;

    const uint32_t smb = (uint32_t)__cvta_generic_to_shared(smc);

    // fold previous layer's BN into per-channel affine (per-CTA, from raw sums)
    if (useAct) {
        const float cnt = (float)Rr;
        float mu  = prevSum[tid] / cnt;
        float var = fmaxf(prevSumsq[tid] / cnt - mu * mu, 0.f);
        float sc  = rsqrtf(var + BN_EPS) * prevG[tid];
        s_scale[tid] = sc;
        s_shift[tid] = prevBeta[tid] - mu * sc;
        __syncthreads();
    }

    // producer mapping: prow = tid>>2 (0..63), pkg = tid&3 (8 k each)
    const int prow = tid >> 2;
    const int pkg = tid & 3;
    const uint32_t swz = (uint32_t)((pkg ^ ((prow >> 1) & 3)) << 4);
    const uint32_t aSlot  = (uint32_t)(prow * 64) + swz;
    const uint32_t bSlot0 = (uint32_t)(prow * 64) + swz;
    const uint32_t bSlot1 = (uint32_t)((prow + 64) * 64) +
                            (uint32_t)((pkg ^ (((prow + 64) >> 1) & 3)) << 4);
    const float* aG = A + (rowBase + prow) * 256 + pkg * 8;
    const float* wG0 = W + (size_t)(colBase + prow) * 256 + pkg * 8;
    const float* wG1 = W + (size_t)(colBase + prow + 64) * 256 + pkg * 8;

    float acc[2][4][4];
    #pragma unroll
    for (int i = 0; i < 2; i++)
        #pragma unroll
        for (int j = 0; j < 4; j++)
            #pragma unroll
            for (int r = 0; r < 4; r++) acc[i][j][r] = 0.f;

    float4 va0, va1, vb0, vb1, vb2, vb3;
    auto loadG = [&](int kb) {
        va0 = *(const float4*)(aG + kb * 32);
        va1 = *(const float4*)(aG + kb * 32 + 4);
        vb0 = *(const float4*)(wG0 + kb * 32);
        vb1 = *(const float4*)(wG0 + kb * 32 + 4);
        vb2 = *(const float4*)(wG1 + kb * 32);
        vb3 = *(const float4*)(wG1 + kb * 32 + 4);
    };
    auto cvt8 = [&](const float* a, uint4& hi, uint4& lo) {
        hi.x = prmt_hi(__float_as_uint(a[0]), __float_as_uint(a[1]));
        hi.y = prmt_hi(__float_as_uint(a[2]), __float_as_uint(a[3]));
        hi.z = prmt_hi(__float_as_uint(a[4]), __float_as_uint(a[5]));
        hi.w = prmt_hi(__float_as_uint(a[6]), __float_as_uint(a[7]));
        lo.x = pack_bf16_rn(a[0] - trunc_hi_f(a[0]), a[1] - trunc_hi_f(a[1]));
        lo.y = pack_bf16_rn(a[2] - trunc_hi_f(a[2]), a[3] - trunc_hi_f(a[3]));
        lo.z = pack_bf16_rn(a[4] - trunc_hi_f(a[4]), a[5] - trunc_hi_f(a[5]));
        lo.w = pack_bf16_rn(a[6] - trunc_hi_f(a[6]), a[7] - trunc_hi_f(a[7]));
    };
    auto storeS = [&](int s, int kb) {
        const uint32_t stg = smb + s * STAGE_B;
        float a[8] = {va0.x, va0.y, va0.z, va0.w, va1.x, va1.y, va1.z, va1.w};
        if (useAct) {
            int c = kb * 32 + pkg * 8;
            #pragma unroll
            for (int j = 0; j < 8; j++)
                a[j] = fmaxf(fmaf(a[j], s_scale[c + j], s_shift[c + j]), 0.f);
        }
        uint4 hi, lo;
        cvt8(a, hi, lo);
        asm volatile("st.shared.v4.b32 [%0], {%1,%2,%3,%4};"
                     :: "r"(stg + aSlot), "r"(hi.x), "r"(hi.y), "r"(hi.z), "r"(hi.w));
        asm volatile("st.shared.v4.b32 [%0], {%1,%2,%3,%4};"
                     :: "r"(stg + A_TILE + aSlot), "r"(lo.x), "r"(lo.y), "r"(lo.z), "r"(lo.w));

        float b0a[8] = {vb0.x, vb0.y, vb0.z, vb0.w, vb1.x, vb1.y, vb1.z, vb1.w};
        cvt8(b0a, hi, lo);
        asm volatile("st.shared.v4.b32 [%0], {%1,%2,%3,%4};"
                     :: "r"(stg + 2 * A_TILE + bSlot0), "r"(hi.x), "r"(hi.y), "r"(hi.z), "r"(hi.w));
        asm volatile("st.shared.v4.b32 [%0], {%1,%2,%3,%4};"
                     :: "r"(stg + 2 * A_TILE + B_TILE + bSlot0), "r"(lo.x), "r"(lo.y), "r"(lo.z), "r"(lo.w));

        float b1a[8] = {vb2.x, vb2.y, vb2.z, vb2.w, vb3.x, vb3.y, vb3.z, vb3.w};
        cvt8(b1a, hi, lo);
        asm volatile("st.shared.v4.b32 [%0], {%1,%2,%3,%4};"
                     :: "r"(stg + 2 * A_TILE + bSlot1), "r"(hi.x), "r"(hi.y), "r"(hi.z), "r"(hi.w));
        asm volatile("st.shared.v4.b32 [%0], {%1,%2,%3,%4};"
                     :: "r"(stg + 2 * A_TILE + B_TILE + bSlot1), "r"(lo.x), "r"(lo.y), "r"(lo.z), "r"(lo.w));
    };

    const int aRow0 = wm * 32 + ((lane >> 3) & 1) * 8 + (lane & 7);
    const int aKh = (lane >> 4) & 1;
    const int bRow0 = wn * 32 + ((lane >> 4) & 1) * 8 + (lane & 7);
    const int bKh = (lane >> 3) & 1;
    uint32_t aOff[2][2], bOff[2][2];
    #pragma unroll
    for (int mt = 0; mt < 2; mt++) {
        int row = aRow0 + mt * 16;
        #pragma unroll
        for (int ks = 0; ks < 2; ks++)
            aOff[mt][ks] = (uint32_t)(row * 64 + ((((ks << 1) + aKh) ^ ((row >> 1) & 3)) << 4));
    }
    #pragma unroll
    for (int p = 0; p < 2; p++) {
        int row = bRow0 + p * 16;
        #pragma unroll
        for (int ks = 0; ks < 2; ks++)
            bOff[p][ks] = (uint32_t)(2 * A_TILE + row * 64 + ((((ks << 1) + bKh) ^ ((row >> 1) & 3)) << 4));
    }

    auto consume = [&](int s) {
        const uint32_t stg = smb + s * STAGE_B;
        uint4 ah[2], al[2], bh[2][2], bl[2][2];
        #pragma unroll
        for (int mt = 0; mt < 2; mt++) {
            LDMATRIX_X4(ah[mt], stg + aOff[mt][0]);
            LDMATRIX_X4(al[mt], stg + aOff[mt][0] + A_TILE);
        }
        #pragma unroll
        for (int p = 0; p < 2; p++) {
            LDMATRIX_X4(bh[0][p], stg + bOff[p][0]);
            LDMATRIX_X4(bl[0][p], stg + bOff[p][0] + B_TILE);
        }
        #pragma unroll
        for (int p = 0; p < 2; p++) {
            LDMATRIX_X4(bh[1][p], stg + bOff[p][1]);
            LDMATRIX_X4(bl[1][p], stg + bOff[p][1] + B_TILE);
        }
        #pragma unroll
        for (int mt = 0; mt < 2; mt++) {
            #pragma unroll
            for (int p = 0; p < 2; p++) {
                MMA_BF16(acc[mt][2*p],   ah[mt], bh[0][p].x, bh[0][p].y);
                MMA_BF16(acc[mt][2*p],   ah[mt], bl[0][p].x, bl[0][p].y);
                MMA_BF16(acc[mt][2*p],   al[mt], bh[0][p].x, bh[0][p].y);
                MMA_BF16(acc[mt][2*p+1], ah[mt], bh[0][p].z, bh[0][p].w);
                MMA_BF16(acc[mt][2*p+1], ah[mt], bl[0][p].z, bl[0][p].w);
                MMA_BF16(acc[mt][2*p+1], al[mt], bh[0][p].z, bh[0][p].w);
            }
        }
        #pragma unroll
        for (int mt = 0; mt < 2; mt++) {
            LDMATRIX_X4(ah[mt], stg + aOff[mt][1]);
            LDMATRIX_X4(al[mt], stg + aOff[mt][1] + A_TILE);
        }
        #pragma unroll
        for (int mt = 0; mt < 2; mt++) {
            #pragma unroll
            for (int p = 0; p < 2; p++) {
                MMA_BF16(acc[mt][2*p],   ah[mt], bh[1][p].x, bh[1][p].y);
                MMA_BF16(acc[mt][2*p],   ah[mt], bl[1][p].x, bl[1][p].y);
                MMA_BF16(acc[mt][2*p],   al[mt], bh[1][p].x, bh[1][p].y);
                MMA_BF16(acc[mt][2*p+1], ah[mt], bh[1][p].z, bh[1][p].w);
                MMA_BF16(acc[mt][2*p+1], ah[mt], bl[1][p].z, bl[1][p].w);
                MMA_BF16(acc[mt][2*p+1], al[mt], bh[1][p].z, bh[1][p].w);
            }
        }
    };

    // prologue
    loadG(0); storeS(0, 0);
    loadG(1); storeS(1, 1);
    __syncthreads();

    // mainloop: one barrier per 2 K-blocks
    #pragma unroll 1
    for (int kbp = 0; kbp < 8; kbp += 2) {
        if (kbp + 2 < 8) loadG(kbp + 2);
        consume(kbp & 3);
        if (kbp + 2 < 8) storeS((kbp + 2) & 3, kbp + 2);
        if (kbp + 3 < 8) loadG(kbp + 3);
        consume((kbp + 1) & 3);
        if (kbp + 3 < 8) storeS((kbp + 3) & 3, kbp + 3);
        if (kbp + 2 < 8) __syncthreads();
    }

    // epilogue: +bias, store, fused per-channel stats
    float sp[8], ssp[8];
    #pragma unroll
    for (int c = 0; c < 8; c++) { sp[c] = 0.f; ssp[c] = 0.f; }

    const int gId = lane >> 2, l4 = lane & 3;
    #pragma unroll
    for (int mt = 0; mt < 2; mt++) {
        size_t row0 = rowBase + wm * 32 + mt * 16 + gId;
        #pragma unroll
        for (int nt = 0; nt < 4; nt++) {
            int col0 = colBase + wn * 32 + nt * 8 + 2 * l4;
            float b0 = bias[col0], b1 = bias[col0 + 1];
            float v00 = acc[mt][nt][0] + b0, v01 = acc[mt][nt][1] + b1;
            float v10 = acc[mt][nt][2] + b0, v11 = acc[mt][nt][3] + b1;
            *(float2*)(out + row0 * O + col0)        = make_float2(v00, v01);
            *(float2*)(out + (row0 + 8) * O + col0)  = make_float2(v10, v11);
            sp[nt * 2 + 0]  += v00 + v10;
            sp[nt * 2 + 1]  += v01 + v11;
            ssp[nt * 2 + 0] += v00 * v00 + v10 * v10;
            ssp[nt * 2 + 1] += v01 * v01 + v11 * v11;
        }
    }
    #pragma unroll
    for (int c = 0; c < 8; c++) {
        #pragma unroll
        for (int mask = 4; mask <= 16; mask <<= 1) {
            sp[c]  += __shfl_xor_sync(0xffffffffu, sp[c],  mask);
            ssp[c] += __shfl_xor_sync(0xffffffffu, ssp[c], mask);
        }
    }
    if (lane < 4) {
        #pragma unroll
        for (int nt = 0; nt < 4; nt++) {
            #pragma unroll
            for (int h = 0; h < 2; h++) {
                int col = colBase + wn * 32 + nt * 8 + 2 * lane + h;
                atomicAdd(&sumArr[col],   sp[nt * 2 + h]);
                atomicAdd(&sumsqArr[col], ssp[nt * 2 + h]);
            }
        }
    }
}

// ---------------------------------------------------------------------------
// final BN+ReLU + transpose [b][n][o] -> [b][o][n] into d_out (O = 128).
// BN2 folded per-block from raw sums.
__global__ void output_kernel(const float* __restrict__ in, float* __restrict__ out,
                              const float* __restrict__ g2, const float* __restrict__ be2) {
    __shared__ float t[32][33];
    __shared__ float s_scale[128], s_shift[128];
    const int b = blockIdx.z;
    const int n0 = blockIdx.x * 32, o0 = blockIdx.y * 32;
    const int tx = threadIdx.x, ty = threadIdx.y; // 32 x 8
    const int tid = ty * 32 + tx;
    if (tid < 128) {
        const float cnt = (float)Rr;
        float mu  = g_sum2[tid] / cnt;
        float var = fmaxf(g_sumsq2[tid] / cnt - mu * mu, 0.f);
        float sc  = rsqrtf(var + BN_EPS) * g2[tid];
        s_scale[tid] = sc;
        s_shift[tid] = be2[tid] - mu * sc;
    }
    __syncthreads();
    #pragma unroll
    for (int k = 0; k < 32; k += 8) {
        int o = o0 + tx;
        float v = in[((size_t)b * Np + n0 + ty + k) * 128 + o];
        t[ty + k][tx] = fmaxf(fmaf(v, s_scale[o], s_shift[o]), 0.f);
    }
    __syncthreads();
    #pragma unroll
    for (int k = 0; k < 32; k += 8)
        out[((size_t)b * 128 + o0 + ty + k) * Np + n0 + tx] = t[tx][ty + k];
}

// ---------------------------------------------------------------------------
extern "C" void kernel_launch(void* const* d_in, const int* in_sizes, int n_in,
                              void* d_out, int out_size) {
    const float* p   = (const float*)d_in[0];
    const float* q   = (const float*)d_in[1];
    const float* x   = (const float*)d_in[2];
    const float* w0  = (const float*)d_in[3];
    const float* b0  = (const float*)d_in[4];
    const float* g0  = (const float*)d_in[5];
    const float* be0 = (const float*)d_in[6];
    const float* w1  = (const float*)d_in[7];
    const float* b1  = (const float*)d_in[8];
    const float* g1  = (const float*)d_in[9];
    const float* be1 = (const float*)d_in[10];
    const float* w2  = (const float*)d_in[11];
    const float* b2  = (const float*)d_in[12];
    const float* g2  = (const float*)d_in[13];
    const float* be2 = (const float*)d_in[14];
    float* out = (float*)d_out;

    float *bufA, *bufB, *xT;
    float *sum0, *sumsq0, *sum1, *sumsq1, *sum2, *sumsq2;
    cudaGetSymbolAddress((void**)&bufA, g_bufA);
    cudaGetSymbolAddress((void**)&bufB, g_bufB);
    cudaGetSymbolAddress((void**)&xT,  g_xT);
    cudaGetSymbolAddress((void**)&sum0, g_sum0);
    cudaGetSymbolAddress((void**)&sumsq0, g_sumsq0);
    cudaGetSymbolAddress((void**)&sum1, g_sum1);
    cudaGetSymbolAddress((void**)&sumsq1, g_sumsq1);
    cudaGetSymbolAddress((void**)&sum2, g_sum2);
    cudaGetSymbolAddress((void**)&sumsq2, g_sumsq2);

    const int Qfloats = Bb * Mp * 3;                    // 24576
    const int Hfloats = Bb * 128 * Np;                  // 8388608
    const int qoff = (out_size >= Qfloats + Hfloats) ? Qfloats : 0;

    cudaFuncSetAttribute(gemm_bf16x3_kernel,
                         cudaFuncAttributeMaxDynamicSharedMemorySize, SMEM_GEMM_BYTES);

    zero_stats_kernel<<<1, 256>>>();
    transpose_x_kernel<<<dim3(Mp / 32, Cc / 32, Bb), dim3(32, 8)>>>(x, xT);
    knn_interp_kernel<<<dim3(Bb, Np / 128), 256>>>(p, q, xT, bufA);

    // layer 0: in bufA (raw), out bufB (256 ch) — stats fused
    gemm_bf16x3_kernel<<<dim3(Rr / 64, 2), 256, SMEM_GEMM_BYTES>>>(
        bufA, w0, b0, nullptr, nullptr, nullptr, nullptr, 0, bufB, 256, sum0, sumsq0);

    // layer 1: in bufB (BN0+ReLU folded per-CTA), out bufA (256 ch)
    gemm_bf16x3_kernel<<<dim3(Rr / 64, 2), 256, SMEM_GEMM_BYTES>>>(
        bufB, w1, b1, sum0, sumsq0, g0, be0, 1, bufA, 256, sum1, sumsq1);

    // layer 2: in bufA (BN1+ReLU folded per-CTA), out bufB (128 ch)
    gemm_bf16x3_kernel<<<dim3(Rr / 64, 1), 256, SMEM_GEMM_BYTES>>>(
        bufA, w2, b2, sum1, sumsq1, g1, be1, 1, bufB, 128, sum2, sumsq2);

    // output: [q | BN2+ReLU(h) transposed to [B,128,N]]
    if (qoff)
        cudaMemcpyAsync(out, q, (size_t)Qfloats * sizeof(float),
                        cudaMemcpyDeviceToDevice);
    output_kernel<<<dim3(Np / 32, 4, Bb), dim3(32, 8)>>>(bufB, out + qoff, g2, be2);
}

// round 13
// speedup vs baseline: 1.3188x; 1.0057x over previous
#include <cuda_runtime.h>
#include <cstddef>
#include <cstdint>

// Problem constants
#define Bb 8
#define Np 8192
#define Mp 1024
#define Cc 256
#define Rr (Bb*Np)       // 65536 rows
#define BN_EPS 1e-5f

// Scratch (static __device__ — no allocations allowed)
__device__ float g_bufA[(size_t)Rr*Cc];     // 64 MB
__device__ float g_bufB[(size_t)Rr*Cc];     // 64 MB
__device__ float g_xT[(size_t)Bb*Mp*Cc];    // 8 MB
__device__ float g_sum0[Cc],  g_sumsq0[Cc];
__device__ float g_sum1[Cc],  g_sumsq1[Cc];
__device__ float g_sum2[Cc],  g_sumsq2[Cc];
__device__ float g_scale[Cc];
__device__ float g_shift[Cc];

// ---------------------------------------------------------------------------
__global__ void zero_stats_kernel() {
    int t = threadIdx.x;
    g_sum0[t] = 0.f; g_sumsq0[t] = 0.f;
    g_sum1[t] = 0.f; g_sumsq1[t] = 0.f;
    g_sum2[t] = 0.f; g_sumsq2[t] = 0.f;
}

// fold BN into per-channel affine from raw sums: one tiny launch per layer
__global__ void bn_finalize_kernel(const float* __restrict__ sum,
                                   const float* __restrict__ sumsq,
                                   const float* __restrict__ g,
                                   const float* __restrict__ beta, int O) {
    int t = threadIdx.x;
    if (t < O) {
        const float cnt = (float)Rr;
        float mu  = sum[t] / cnt;
        float var = fmaxf(sumsq[t] / cnt - mu * mu, 0.f);
        float sc  = rsqrtf(var + BN_EPS) * g[t];
        g_scale[t] = sc;
        g_shift[t] = beta[t] - mu * sc;
    }
}

// ---------------------------------------------------------------------------
// transpose x[b][c][m] -> xT[b][m][c]
__global__ void transpose_x_kernel(const float* __restrict__ x, float* __restrict__ xT) {
    __shared__ float t[32][33];
    int b = blockIdx.z;
    int m0 = blockIdx.x * 32, c0 = blockIdx.y * 32;
    int tx = threadIdx.x, ty = threadIdx.y; // 32 x 8
    const float* xb = x + (size_t)b * Cc * Mp;
    #pragma unroll
    for (int k = 0; k < 32; k += 8)
        t[ty + k][tx] = xb[(size_t)(c0 + ty + k) * Mp + m0 + tx];
    __syncthreads();
    float* ob = xT + (size_t)b * Mp * Cc;
    #pragma unroll
    for (int k = 0; k < 32; k += 8)
        ob[(size_t)(m0 + ty + k) * Cc + c0 + tx] = t[tx][ty + k];
}

// ---------------------------------------------------------------------------
// 3-NN + inverse-distance-weighted interpolation. Writes h0 in [b][n][c].
// 256 threads: two threads split each point's scan (512 each, even/odd ILP
// chains), merge in smem; gather with 8 warps.
__global__ void knn_interp_kernel(const float* __restrict__ p,
                                  const float* __restrict__ q,
                                  const float* __restrict__ xT,
                                  float* __restrict__ h0) {
    __shared__ float sqx[Mp], sqy[Mp], sqz[Mp], sqq[Mp];
    __shared__ float sd[256][3];
    __shared__ int   sdi[256][3];
    __shared__ float sw[128][3];
    __shared__ int   si[128][3];
    const int b = blockIdx.x;
    const int n0 = blockIdx.y * 128;
    const int tid = threadIdx.x;       // 256

    for (int m = tid; m < Mp; m += 256) {
        float qx = q[((size_t)b * Mp + m) * 3 + 0];
        float qy = q[((size_t)b * Mp + m) * 3 + 1];
        float qz = q[((size_t)b * Mp + m) * 3 + 2];
        sqx[m] = qx; sqy[m] = qy; sqz[m] = qz;
        sqq[m] = qx * qx + qy * qy + qz * qz;
    }
    __syncthreads();

    const int pt = tid & 127;          // point index
    const int half = tid >> 7;         // scan half
    const int n = n0 + pt;
    float px = p[((size_t)b * Np + n) * 3 + 0];
    float py = p[((size_t)b * Np + n) * 3 + 1];
    float pz = p[((size_t)b * Np + n) * 3 + 2];
    float pp = px * px + py * py + pz * pz;

    float e0 = 3.4e38f, e1 = 3.4e38f, e2 = 3.4e38f;
    int   ei0 = 0, ei1 = 0, ei2 = 0;
    float o0 = 3.4e38f, o1 = 3.4e38f, o2 = 3.4e38f;
    int   oi0 = 0, oi1 = 0, oi2 = 0;
    const int mBase = half * 512;
    #pragma unroll 2
    for (int m = mBase; m < mBase + 512; m += 2) {
        float dotE = px * sqx[m] + py * sqy[m] + pz * sqz[m];
        float dE = pp + sqq[m] - 2.f * dotE;
        float dotO = px * sqx[m+1] + py * sqy[m+1] + pz * sqz[m+1];
        float dO = pp + sqq[m+1] - 2.f * dotO;
        if (dE < e2) {
            if (dE < e1) {
                e2 = e1; ei2 = ei1;
                if (dE < e0) { e1 = e0; ei1 = ei0; e0 = dE; ei0 = m; }
                else         { e1 = dE; ei1 = m; }
            } else { e2 = dE; ei2 = m; }
        }
        if (dO < o2) {
            if (dO < o1) {
                o2 = o1; oi2 = oi1;
                if (dO < o0) { o1 = o0; oi1 = oi0; o0 = dO; oi0 = m+1; }
                else         { o1 = dO; oi1 = m+1; }
            } else { o2 = dO; oi2 = m+1; }
        }
    }
    // merge odd chain into even chain (within this half)
    #pragma unroll
    for (int c = 0; c < 3; c++) {
        float d = (c == 0) ? o0 : (c == 1) ? o1 : o2;
        int   i = (c == 0) ? oi0 : (c == 1) ? oi1 : oi2;
        if (d < e2) {
            if (d < e1) {
                e2 = e1; ei2 = ei1;
                if (d < e0) { e1 = e0; ei1 = ei0; e0 = d; ei0 = i; }
                else        { e1 = d; ei1 = i; }
            } else { e2 = d; ei2 = i; }
        }
    }
    sd[tid][0] = e0;  sd[tid][1] = e1;  sd[tid][2] = e2;
    sdi[tid][0] = ei0; sdi[tid][1] = ei1; sdi[tid][2] = ei2;
    __syncthreads();

    if (tid < 128) {
        float m0 = sd[tid][0], m1 = sd[tid][1], m2 = sd[tid][2];
        int   j0 = sdi[tid][0], j1 = sdi[tid][1], j2 = sdi[tid][2];
        #pragma unroll
        for (int c = 0; c < 3; c++) {
            float d = sd[tid + 128][c];
            int   i = sdi[tid + 128][c];
            if (d < m2) {
                if (d < m1) {
                    m2 = m1; j2 = j1;
                    if (d < m0) { m1 = m0; j1 = j0; m0 = d; j0 = i; }
                    else        { m1 = d; j1 = i; }
                } else { m2 = d; j2 = i; }
            }
        }
        float a0 = 1.f / fmaxf(m0, 1e-10f);
        float a1 = 1.f / fmaxf(m1, 1e-10f);
        float a2 = 1.f / fmaxf(m2, 1e-10f);
        float inv = 1.f / (a0 + a1 + a2);
        sw[tid][0] = a0 * inv; sw[tid][1] = a1 * inv; sw[tid][2] = a2 * inv;
        si[tid][0] = j0; si[tid][1] = j1; si[tid][2] = j2;
    }
    __syncthreads();

    const int lane = tid & 31, warp = tid >> 5;   // 8 warps x 16 points
    const float* xb = xT + (size_t)b * Mp * Cc;
    for (int nl = warp * 16; nl < warp * 16 + 16; nl++) {
        float w0 = sw[nl][0], w1 = sw[nl][1], w2 = sw[nl][2];
        const float4* r0 = (const float4*)(xb + (size_t)si[nl][0] * Cc);
        const float4* r1 = (const float4*)(xb + (size_t)si[nl][1] * Cc);
        const float4* r2 = (const float4*)(xb + (size_t)si[nl][2] * Cc);
        float4* o4 = (float4*)(h0 + ((size_t)b * Np + n0 + nl) * Cc);
        #pragma unroll
        for (int c = lane; c < Cc / 4; c += 32) {
            float4 a = r0[c], bq = r1[c], cq = r2[c];
            float4 v;
            v.x = w0 * a.x + w1 * bq.x + w2 * cq.x;
            v.y = w0 * a.y + w1 * bq.y + w2 * cq.y;
            v.z = w0 * a.z + w1 * bq.z + w2 * cq.z;
            v.w = w0 * a.w + w1 * bq.w + w2 * cq.w;
            o4[c] = v;
        }
    }
}

// ---------------------------------------------------------------------------
// bf16x3 emulated-fp32 GEMM via legacy mma.sync (sm_80 PTX path)
// ---------------------------------------------------------------------------
__device__ __forceinline__ uint32_t prmt_hi(uint32_t a, uint32_t b) {
    uint32_t r; asm("prmt.b32 %0, %1, %2, 0x7632;" : "=r"(r) : "r"(a), "r"(b));
    return r;   // {lo16 = a.hi16, hi16 = b.hi16}
}
__device__ __forceinline__ uint32_t pack_bf16_rn(float lo0, float lo1) {
    uint32_t r; asm("cvt.rn.bf16x2.f32 %0, %1, %2;" : "=r"(r) : "f"(lo1), "f"(lo0));
    return r;   // low half = lo0
}
__device__ __forceinline__ float trunc_hi_f(float f) {
    return __uint_as_float(__float_as_uint(f) & 0xFFFF0000u);
}

#define MMA_BF16(c, a, b0v, b1v) \
    asm volatile("mma.sync.aligned.m16n8k16.row.col.f32.bf16.bf16.f32 " \
        "{%0,%1,%2,%3},{%4,%5,%6,%7},{%8,%9},{%0,%1,%2,%3};" \
        : "+f"((c)[0]), "+f"((c)[1]), "+f"((c)[2]), "+f"((c)[3]) \
        : "r"((a).x), "r"((a).y), "r"((a).z), "r"((a).w), "r"(b0v), "r"(b1v))

#define LDMATRIX_X4(r, addr) \
    asm volatile("ldmatrix.sync.aligned.m8n8.x4.shared.b16 {%0,%1,%2,%3}, [%4];" \
        : "=r"((r).x), "=r"((r).y), "=r"((r).z), "=r"((r).w) : "r"(addr))

// smem tiles: bf16, row-major, rows x 32 k = 64 B/row, XOR-granule swizzle.
// Stage layout: A_hi(4K) A_lo(4K) B_hi(8K) B_lo(8K) = 24 KB; 4 stages = 96 KB.
#define A_TILE   4096
#define B_TILE   8192
#define STAGE_B  (2 * A_TILE + 2 * B_TILE)   // 24576
#define SMEM_GEMM_BYTES (4 * STAGE_B)        // 98304

// out[r][o] = sum_c act(A[r][c]) * W[o][c] + bias[o], K=256, CTA tile 64x128.
// 256 threads, 8 warps (2M x 4N), 2 CTAs/SM, 4-stage ring, barrier per 2 kb.
// Prev-layer BN+ReLU applied from precomputed g_scale/g_shift (R10 style);
// BN stats fused into epilogue (per-layer arrays).
__global__ void __launch_bounds__(256, 2)
gemm_bf16x3_kernel(const float* __restrict__ A, const float* __restrict__ W,
                   const float* __restrict__ bias, int useAct,
                   float* __restrict__ out, int O,
                   float* __restrict__ sumArr, float* __restrict__ sumsqArr) {
    extern __shared__ char smc[];
    const int tid = threadIdx.x;
    const int lane = tid & 31, wid = tid >> 5;
    const int wm = wid >> 2, wn = wid & 3;           // 2M x 4N
    const size_t rowBase = (size_t)blockIdx.x * 64;
    const int colBase = blockIdx.y * 128;

    const uint32_t smb = (uint32_t)__cvta_generic_to_shared(smc);

    // producer mapping: prow = tid>>2 (0..63), pkg = tid&3 (8 k each)
    const int prow = tid >> 2;
    const int pkg = tid & 3;
    const uint32_t swz = (uint32_t)((pkg ^ ((prow >> 1) & 3)) << 4);
    const uint32_t aSlot  = (uint32_t)(prow * 64) + swz;
    const uint32_t bSlot0 = (uint32_t)(prow * 64) + swz;
    const uint32_t bSlot1 = (uint32_t)((prow + 64) * 64) +
                            (uint32_t)((pkg ^ (((prow + 64) >> 1) & 3)) << 4);
    const float* aG = A + (rowBase + prow) * 256 + pkg * 8;
    const float* wG0 = W + (size_t)(colBase + prow) * 256 + pkg * 8;
    const float* wG1 = W + (size_t)(colBase + prow + 64) * 256 + pkg * 8;

    float acc[2][4][4];
    #pragma unroll
    for (int i = 0; i < 2; i++)
        #pragma unroll
        for (int j = 0; j < 4; j++)
            #pragma unroll
            for (int r = 0; r < 4; r++) acc[i][j][r] = 0.f;

    float4 va0, va1, vb0, vb1, vb2, vb3;
    auto loadG = [&](int kb) {
        va0 = *(const float4*)(aG + kb * 32);
        va1 = *(const float4*)(aG + kb * 32 + 4);
        vb0 = *(const float4*)(wG0 + kb * 32);
        vb1 = *(const float4*)(wG0 + kb * 32 + 4);
        vb2 = *(const float4*)(wG1 + kb * 32);
        vb3 = *(const float4*)(wG1 + kb * 32 + 4);
    };
    auto cvt8 = [&](const float* a, uint4& hi, uint4& lo) {
        hi.x = prmt_hi(__float_as_uint(a[0]), __float_as_uint(a[1]));
        hi.y = prmt_hi(__float_as_uint(a[2]), __float_as_uint(a[3]));
        hi.z = prmt_hi(__float_as_uint(a[4]), __float_as_uint(a[5]));
        hi.w = prmt_hi(__float_as_uint(a[6]), __float_as_uint(a[7]));
        lo.x = pack_bf16_rn(a[0] - trunc_hi_f(a[0]), a[1] - trunc_hi_f(a[1]));
        lo.y = pack_bf16_rn(a[2] - trunc_hi_f(a[2]), a[3] - trunc_hi_f(a[3]));
        lo.z = pack_bf16_rn(a[4] - trunc_hi_f(a[4]), a[5] - trunc_hi_f(a[5]));
        lo.w = pack_bf16_rn(a[6] - trunc_hi_f(a[6]), a[7] - trunc_hi_f(a[7]));
    };
    auto storeS = [&](int s, int kb) {
        const uint32_t stg = smb + s * STAGE_B;
        float a[8] = {va0.x, va0.y, va0.z, va0.w, va1.x, va1.y, va1.z, va1.w};
        if (useAct) {
            int c = kb * 32 + pkg * 8;
            #pragma unroll
            for (int j = 0; j < 8; j++)
                a[j] = fmaxf(fmaf(a[j], g_scale[c + j], g_shift[c + j]), 0.f);
        }
        uint4 hi, lo;
        cvt8(a, hi, lo);
        asm volatile("st.shared.v4.b32 [%0], {%1,%2,%3,%4};"
                     :: "r"(stg + aSlot), "r"(hi.x), "r"(hi.y), "r"(hi.z), "r"(hi.w));
        asm volatile("st.shared.v4.b32 [%0], {%1,%2,%3,%4};"
                     :: "r"(stg + A_TILE + aSlot), "r"(lo.x), "r"(lo.y), "r"(lo.z), "r"(lo.w));

        float b0a[8] = {vb0.x, vb0.y, vb0.z, vb0.w, vb1.x, vb1.y, vb1.z, vb1.w};
        cvt8(b0a, hi, lo);
        asm volatile("st.shared.v4.b32 [%0], {%1,%2,%3,%4};"
                     :: "r"(stg + 2 * A_TILE + bSlot0), "r"(hi.x), "r"(hi.y), "r"(hi.z), "r"(hi.w));
        asm volatile("st.shared.v4.b32 [%0], {%1,%2,%3,%4};"
                     :: "r"(stg + 2 * A_TILE + B_TILE + bSlot0), "r"(lo.x), "r"(lo.y), "r"(lo.z), "r"(lo.w));

        float b1a[8] = {vb2.x, vb2.y, vb2.z, vb2.w, vb3.x, vb3.y, vb3.z, vb3.w};
        cvt8(b1a, hi, lo);
        asm volatile("st.shared.v4.b32 [%0], {%1,%2,%3,%4};"
                     :: "r"(stg + 2 * A_TILE + bSlot1), "r"(hi.x), "r"(hi.y), "r"(hi.z), "r"(hi.w));
        asm volatile("st.shared.v4.b32 [%0], {%1,%2,%3,%4};"
                     :: "r"(stg + 2 * A_TILE + B_TILE + bSlot1), "r"(lo.x), "r"(lo.y), "r"(lo.z), "r"(lo.w));
    };

    const int aRow0 = wm * 32 + ((lane >> 3) & 1) * 8 + (lane & 7);
    const int aKh = (lane >> 4) & 1;
    const int bRow0 = wn * 32 + ((lane >> 4) & 1) * 8 + (lane & 7);
    const int bKh = (lane >> 3) & 1;
    uint32_t aOff[2][2], bOff[2][2];
    #pragma unroll
    for (int mt = 0; mt < 2; mt++) {
        int row = aRow0 + mt * 16;
        #pragma unroll
        for (int ks = 0; ks < 2; ks++)
            aOff[mt][ks] = (uint32_t)(row * 64 + ((((ks << 1) + aKh) ^ ((row >> 1) & 3)) << 4));
    }
    #pragma unroll
    for (int p = 0; p < 2; p++) {
        int row = bRow0 + p * 16;
        #pragma unroll
        for (int ks = 0; ks < 2; ks++)
            bOff[p][ks] = (uint32_t)(2 * A_TILE + row * 64 + ((((ks << 1) + bKh) ^ ((row >> 1) & 3)) << 4));
    }

    auto consume = [&](int s) {
        const uint32_t stg = smb + s * STAGE_B;
        uint4 ah[2], al[2], bh[2][2], bl[2][2];
        #pragma unroll
        for (int mt = 0; mt < 2; mt++) {
            LDMATRIX_X4(ah[mt], stg + aOff[mt][0]);
            LDMATRIX_X4(al[mt], stg + aOff[mt][0] + A_TILE);
        }
        #pragma unroll
        for (int p = 0; p < 2; p++) {
            LDMATRIX_X4(bh[0][p], stg + bOff[p][0]);
            LDMATRIX_X4(bl[0][p], stg + bOff[p][0] + B_TILE);
        }
        #pragma unroll
        for (int p = 0; p < 2; p++) {
            LDMATRIX_X4(bh[1][p], stg + bOff[p][1]);
            LDMATRIX_X4(bl[1][p], stg + bOff[p][1] + B_TILE);
        }
        #pragma unroll
        for (int mt = 0; mt < 2; mt++) {
            #pragma unroll
            for (int p = 0; p < 2; p++) {
                MMA_BF16(acc[mt][2*p],   ah[mt], bh[0][p].x, bh[0][p].y);
                MMA_BF16(acc[mt][2*p],   ah[mt], bl[0][p].x, bl[0][p].y);
                MMA_BF16(acc[mt][2*p],   al[mt], bh[0][p].x, bh[0][p].y);
                MMA_BF16(acc[mt][2*p+1], ah[mt], bh[0][p].z, bh[0][p].w);
                MMA_BF16(acc[mt][2*p+1], ah[mt], bl[0][p].z, bl[0][p].w);
                MMA_BF16(acc[mt][2*p+1], al[mt], bh[0][p].z, bh[0][p].w);
            }
        }
        #pragma unroll
        for (int mt = 0; mt < 2; mt++) {
            LDMATRIX_X4(ah[mt], stg + aOff[mt][1]);
            LDMATRIX_X4(al[mt], stg + aOff[mt][1] + A_TILE);
        }
        #pragma unroll
        for (int mt = 0; mt < 2; mt++) {
            #pragma unroll
            for (int p = 0; p < 2; p++) {
                MMA_BF16(acc[mt][2*p],   ah[mt], bh[1][p].x, bh[1][p].y);
                MMA_BF16(acc[mt][2*p],   ah[mt], bl[1][p].x, bl[1][p].y);
                MMA_BF16(acc[mt][2*p],   al[mt], bh[1][p].x, bh[1][p].y);
                MMA_BF16(acc[mt][2*p+1], ah[mt], bh[1][p].z, bh[1][p].w);
                MMA_BF16(acc[mt][2*p+1], ah[mt], bl[1][p].z, bl[1][p].w);
                MMA_BF16(acc[mt][2*p+1], al[mt], bh[1][p].z, bh[1][p].w);
            }
        }
    };

    // prologue
    loadG(0); storeS(0, 0);
    loadG(1); storeS(1, 1);
    __syncthreads();

    // mainloop: one barrier per 2 K-blocks
    #pragma unroll 1
    for (int kbp = 0; kbp < 8; kbp += 2) {
        if (kbp + 2 < 8) loadG(kbp + 2);
        consume(kbp & 3);
        if (kbp + 2 < 8) storeS((kbp + 2) & 3, kbp + 2);
        if (kbp + 3 < 8) loadG(kbp + 3);
        consume((kbp + 1) & 3);
        if (kbp + 3 < 8) storeS((kbp + 3) & 3, kbp + 3);
        if (kbp + 2 < 8) __syncthreads();
    }

    // epilogue: +bias, store, fused per-channel stats
    float sp[8], ssp[8];
    #pragma unroll
    for (int c = 0; c < 8; c++) { sp[c] = 0.f; ssp[c] = 0.f; }

    const int gId = lane >> 2, l4 = lane & 3;
    #pragma unroll
    for (int mt = 0; mt < 2; mt++) {
        size_t row0 = rowBase + wm * 32 + mt * 16 + gId;
        #pragma unroll
        for (int nt = 0; nt < 4; nt++) {
            int col0 = colBase + wn * 32 + nt * 8 + 2 * l4;
            float b0 = bias[col0], b1 = bias[col0 + 1];
            float v00 = acc[mt][nt][0] + b0, v01 = acc[mt][nt][1] + b1;
            float v10 = acc[mt][nt][2] + b0, v11 = acc[mt][nt][3] + b1;
            *(float2*)(out + row0 * O + col0)        = make_float2(v00, v01);
            *(float2*)(out + (row0 + 8) * O + col0)  = make_float2(v10, v11);
            sp[nt * 2 + 0]  += v00 + v10;
            sp[nt * 2 + 1]  += v01 + v11;
            ssp[nt * 2 + 0] += v00 * v00 + v10 * v10;
            ssp[nt * 2 + 1] += v01 * v01 + v11 * v11;
        }
    }
    #pragma unroll
    for (int c = 0; c < 8; c++) {
        #pragma unroll
        for (int mask = 4; mask <= 16; mask <<= 1) {
            sp[c]  += __shfl_xor_sync(0xffffffffu, sp[c],  mask);
            ssp[c] += __shfl_xor_sync(0xffffffffu, ssp[c], mask);
        }
    }
    if (lane < 4) {
        #pragma unroll
        for (int nt = 0; nt < 4; nt++) {
            #pragma unroll
            for (int h = 0; h < 2; h++) {
                int col = colBase + wn * 32 + nt * 8 + 2 * lane + h;
                atomicAdd(&sumArr[col],   sp[nt * 2 + h]);
                atomicAdd(&sumsqArr[col], ssp[nt * 2 + h]);
            }
        }
    }
}

// ---------------------------------------------------------------------------
// final BN+ReLU + transpose [b][n][o] -> [b][o][n] into d_out (O = 128).
// Uses g_scale/g_shift prepared by bn_finalize for layer 2.
__global__ void output_kernel(const float* __restrict__ in, float* __restrict__ out) {
    __shared__ float t[32][33];
    const int b = blockIdx.z;
    const int n0 = blockIdx.x * 32, o0 = blockIdx.y * 32;
    const int tx = threadIdx.x, ty = threadIdx.y; // 32 x 8
    #pragma unroll
    for (int k = 0; k < 32; k += 8) {
        int o = o0 + tx;
        float v = in[((size_t)b * Np + n0 + ty + k) * 128 + o];
        t[ty + k][tx] = fmaxf(fmaf(v, g_scale[o], g_shift[o]), 0.f);
    }
    __syncthreads();
    #pragma unroll
    for (int k = 0; k < 32; k += 8)
        out[((size_t)b * 128 + o0 + ty + k) * Np + n0 + tx] = t[tx][ty + k];
}

// ---------------------------------------------------------------------------
extern "C" void kernel_launch(void* const* d_in, const int* in_sizes, int n_in,
                              void* d_out, int out_size) {
    const float* p   = (const float*)d_in[0];
    const float* q   = (const float*)d_in[1];
    const float* x   = (const float*)d_in[2];
    const float* w0  = (const float*)d_in[3];
    const float* b0  = (const float*)d_in[4];
    const float* g0  = (const float*)d_in[5];
    const float* be0 = (const float*)d_in[6];
    const float* w1  = (const float*)d_in[7];
    const float* b1  = (const float*)d_in[8];
    const float* g1  = (const float*)d_in[9];
    const float* be1 = (const float*)d_in[10];
    const float* w2  = (const float*)d_in[11];
    const float* b2  = (const float*)d_in[12];
    const float* g2  = (const float*)d_in[13];
    const float* be2 = (const float*)d_in[14];
    float* out = (float*)d_out;

    float *bufA, *bufB, *xT;
    float *sum0, *sumsq0, *sum1, *sumsq1, *sum2, *sumsq2;
    cudaGetSymbolAddress((void**)&bufA, g_bufA);
    cudaGetSymbolAddress((void**)&bufB, g_bufB);
    cudaGetSymbolAddress((void**)&xT,  g_xT);
    cudaGetSymbolAddress((void**)&sum0, g_sum0);
    cudaGetSymbolAddress((void**)&sumsq0, g_sumsq0);
    cudaGetSymbolAddress((void**)&sum1, g_sum1);
    cudaGetSymbolAddress((void**)&sumsq1, g_sumsq1);
    cudaGetSymbolAddress((void**)&sum2, g_sum2);
    cudaGetSymbolAddress((void**)&sumsq2, g_sumsq2);

    const int Qfloats = Bb * Mp * 3;                    // 24576
    const int Hfloats = Bb * 128 * Np;                  // 8388608
    const int qoff = (out_size >= Qfloats + Hfloats) ? Qfloats : 0;

    cudaFuncSetAttribute(gemm_bf16x3_kernel,
                         cudaFuncAttributeMaxDynamicSharedMemorySize, SMEM_GEMM_BYTES);

    zero_stats_kernel<<<1, 256>>>();
    transpose_x_kernel<<<dim3(Mp / 32, Cc / 32, Bb), dim3(32, 8)>>>(x, xT);
    knn_interp_kernel<<<dim3(Bb, Np / 128), 256>>>(p, q, xT, bufA);

    // layer 0: in bufA (raw), out bufB (256 ch) — stats fused
    gemm_bf16x3_kernel<<<dim3(Rr / 64, 2), 256, SMEM_GEMM_BYTES>>>(
        bufA, w0, b0, 0, bufB, 256, sum0, sumsq0);
    bn_finalize_kernel<<<1, 256>>>(sum0, sumsq0, g0, be0, 256);

    // layer 1: in bufB (BN0+ReLU via g_scale/g_shift), out bufA (256 ch)
    gemm_bf16x3_kernel<<<dim3(Rr / 64, 2), 256, SMEM_GEMM_BYTES>>>(
        bufB, w1, b1, 1, bufA, 256, sum1, sumsq1);
    bn_finalize_kernel<<<1, 256>>>(sum1, sumsq1, g1, be1, 256);

    // layer 2: in bufA (BN1+ReLU via g_scale/g_shift), out bufB (128 ch)
    gemm_bf16x3_kernel<<<dim3(Rr / 64, 1), 256, SMEM_GEMM_BYTES>>>(
        bufA, w2, b2, 1, bufB, 128, sum2, sumsq2);
    bn_finalize_kernel<<<1, 256>>>(sum2, sumsq2, g2, be2, 128);

    // output: [q | BN2+ReLU(h) transposed to [B,128,N]]
    if (qoff)
        cudaMemcpyAsync(out, q, (size_t)Qfloats * sizeof(float),
                        cudaMemcpyDeviceToDevice);
    output_kernel<<<dim3(Np / 32, 4, Bb), dim3(32, 8)>>>(bufB, out + qoff);
}